// round 12
// baseline (speedup 1.0000x reference)
#include <cuda_runtime.h>
#include <cuda_fp16.h>
#include <math.h>
#include <stdint.h>

#define B_  2
#define T_  2048
#define EMB 1024
#define H_  16
#define D_  64
#define M_  (B_ * T_)          // 4096
#define N1  3072
#define N2  1024
#define SCALE 0.125f

// ---------------- scratch (u32 = fp16x2, hi-only) ----------------
__device__ uint32_t g_xh[4096 * 512];        // x  [m][kpair]
__device__ uint32_t g_wqh[3072 * 512];       // Wqkv^T [n][kpair]
__device__ uint32_t g_woh[1024 * 512];       // Wout^T [n][kpair]
__device__ uint32_t g_Qh[2097152];           // [bh][t][32 dpair]
__device__ uint32_t g_Kh[2097152];           // [bh][t][32 dpair]
__device__ uint32_t g_Vh[2097152];           // [bh][64 d][1024 tpair]
__device__ uint32_t g_Oh[2097152];           // [m][512 kpair]

// ---------------- helpers ----------------
__device__ __forceinline__ uint32_t pack2(float x, float y) {   // low=x, high=y
    uint32_t r;
    asm("cvt.rn.f16x2.f32 %0, %1, %2;" : "=r"(r) : "f"(y), "f"(x));
    return r;
}
__device__ __forceinline__ void mma16(float* c, const uint32_t* a, const uint32_t* b) {
    asm volatile(
        "mma.sync.aligned.m16n8k16.row.col.f32.f16.f16.f32 "
        "{%0,%1,%2,%3},{%4,%5,%6,%7},{%8,%9},{%0,%1,%2,%3};\n"
        : "+f"(c[0]), "+f"(c[1]), "+f"(c[2]), "+f"(c[3])
        : "r"(a[0]), "r"(a[1]), "r"(a[2]), "r"(a[3]), "r"(b[0]), "r"(b[1]));
}
__device__ __forceinline__ void ldsm4(uint32_t* r, uint32_t saddr) {
    asm volatile("ldmatrix.sync.aligned.m8n8.x4.shared.b16 {%0,%1,%2,%3}, [%4];"
                 : "=r"(r[0]), "=r"(r[1]), "=r"(r[2]), "=r"(r[3]) : "r"(saddr));
}
__device__ __forceinline__ uint32_t sptr(const void* p) {
    return (uint32_t)__cvta_generic_to_shared(p);
}
__device__ __forceinline__ void cp16(uint32_t saddr, const void* g) {
    asm volatile("cp.async.cg.shared.global [%0], [%1], 16;\n" :: "r"(saddr), "l"(g));
}
#define CP_COMMIT() asm volatile("cp.async.commit_group;\n" ::)
#define CP_WAIT1()  asm volatile("cp.async.wait_group 1;\n" ::)

// ---------------- merged prep kernel ----------------
// blocks [0, 8192): prep_x; [8192, 8960): Wqkv transpose; [8960, 9216): Wout.
__global__ __launch_bounds__(256) void prep_all(const float* __restrict__ x,
                                                const float* __restrict__ Wqkv,
                                                const float* __restrict__ Wout)
{
    __shared__ uint32_t sh[64][33];
    const int tid = threadIdx.x;
    const int bid = blockIdx.x;

    if (bid < 8192) {
        int i = bid * 256 + tid;
        float2 v = ((const float2*)x)[i];
        g_xh[i] = pack2(v.x, v.y);
        return;
    }
    const float* W;
    uint32_t* Dh;
    int N, n0, kp0;
    if (bid < 8960) {
        int b2 = bid - 8192;            // grid (48, 16)
        W = Wqkv; Dh = g_wqh; N = N1;
        n0 = (b2 % 48) * 64;  kp0 = (b2 / 48) * 32;
    } else {
        int b3 = bid - 8960;            // grid (16, 16)
        W = Wout; Dh = g_woh; N = N2;
        n0 = (b3 % 16) * 64;  kp0 = (b3 / 16) * 32;
    }
#pragma unroll
    for (int r = 0; r < 8; r++) {
        int kp = r * 4 + (tid >> 6);
        int n  = tid & 63;
        float a = W[(size_t)(2 * (kp0 + kp))     * N + n0 + n];
        float b = W[(size_t)(2 * (kp0 + kp) + 1) * N + n0 + n];
        sh[n][kp] = pack2(a, b);
    }
    __syncthreads();
#pragma unroll
    for (int w = 0; w < 8; w++) {
        int n = w * 8 + (tid >> 5), c = tid & 31;
        Dh[(size_t)(n0 + n) * 512 + kp0 + c] = sh[n][c];
    }
}

// ================= GEMM (1-pass fp16, 64x64 warp tiles) ====================
// Block 128x128, 4 warps (2x2), warp tile 64x64, BK=32 (16 kpairs), 128 thr.
#define GS 20
#define G_BHI 2560
#define G_STAGE 5120
#define GEMM_SMEM (2 * G_STAGE * 4)

__device__ __forceinline__ void g_load_stage(uint32_t sbase, int kb, int bm, int bn, int tid,
                                             const uint32_t* __restrict__ Ah,
                                             const uint32_t* __restrict__ Wh)
{
#pragma unroll
    for (int j = 0; j < 4; j++) {
        int idx = tid + j * 128;          // 0..511
        int row = idx >> 2, c = (idx & 3) * 4;
        size_t srcA = (size_t)(bm + row) * 512 + kb * 16 + c;
        size_t srcB = (size_t)(bn + row) * 512 + kb * 16 + c;
        uint32_t off = (row * GS + c) * 4;
        cp16(sbase + off,             &Ah[srcA]);
        cp16(sbase + G_BHI * 4 + off, &Wh[srcB]);
    }
}

template<int MODE>
__global__ __launch_bounds__(128, 2) void gemmb(const float* __restrict__ bias,
                                                float* __restrict__ C)
{
    extern __shared__ uint32_t smem_g[];
    const uint32_t* Ah = (MODE == 0) ? g_xh  : g_Oh;
    const uint32_t* Wh = (MODE == 0) ? g_wqh : g_woh;

    const int tid  = threadIdx.x;
    const int warp = tid >> 5, lane = tid & 31;
    const int g    = lane >> 2, tg = lane & 3;
    const int wy   = warp >> 1, wx = warp & 1;      // 2 x 2 warps
    const int bm   = blockIdx.y * 128, bn = blockIdx.x * 128;

    float acc[4][8][4];
#pragma unroll
    for (int i = 0; i < 4; i++)
#pragma unroll
        for (int j = 0; j < 8; j++)
#pragma unroll
            for (int r = 0; r < 4; r++) acc[i][j][r] = 0.f;

    const uint32_t sbase = sptr(smem_g);
    const int a_row = wy * 64 + (lane & 15);
    const int a_col = (lane >> 4) * 4;
    const int b_row = wx * 64 + ((lane >> 4) & 1) * 8 + (lane & 7);
    const int b_col = ((lane >> 3) & 1) * 4;

    g_load_stage(sbase, 0, bm, bn, tid, Ah, Wh);
    CP_COMMIT();
    g_load_stage(sbase + G_STAGE * 4, 1, bm, bn, tid, Ah, Wh);
    CP_COMMIT();

    for (int kb = 0; kb < 32; kb++) {
        CP_WAIT1();
        __syncthreads();
        const uint32_t st = sbase + (kb & 1) * (G_STAGE * 4);

#pragma unroll
        for (int ka = 0; ka < 2; ka++) {
            uint32_t bb4[4][4];
#pragma unroll
            for (int nb = 0; nb < 4; nb++)
                ldsm4(bb4[nb], st + G_BHI * 4 + ((b_row + nb * 16) * GS + ka * 8 + b_col) * 4);
#pragma unroll
            for (int ma = 0; ma < 4; ma++) {
                uint32_t ah[4];
                ldsm4(ah, st + ((a_row + ma * 16) * GS + ka * 8 + a_col) * 4);
#pragma unroll
                for (int na = 0; na < 8; na++)
                    mma16(acc[ma][na], ah, &bb4[na >> 1][(na & 1) * 2]);
            }
        }
        __syncthreads();
        if (kb + 2 < 32)
            g_load_stage(st, kb + 2, bm, bn, tid, Ah, Wh);
        CP_COMMIT();
    }

    // ---------- epilogue ----------
#pragma unroll
    for (int ma = 0; ma < 4; ma++) {
        int m0 = bm + wy * 64 + ma * 16 + g;
#pragma unroll
        for (int na = 0; na < 8; na++) {
            int n = bn + wx * 64 + na * 8 + tg * 2;
            float b0v = bias[n], b1v = bias[n + 1];
#pragma unroll
            for (int half = 0; half < 2; half++) {
                int m = m0 + half * 8;
                float vx = acc[ma][na][half * 2 + 0] + b0v;
                float vy = acc[ma][na][half * 2 + 1] + b1v;
                if (MODE == 0) {
                    int bb2 = m >> 11, t = m & (T_ - 1);
                    int sec = n >> 10, rem = n & 1023;
                    int h = rem >> 6, d = rem & 63;
                    int bhh = bb2 * H_ + h;
                    if (sec == 0) {
                        size_t idx = ((size_t)bhh * T_ + t) * 32 + (d >> 1);
                        g_Qh[idx] = pack2(vx * SCALE, vy * SCALE);
                    } else if (sec == 1) {
                        size_t idx = ((size_t)bhh * T_ + t) * 32 + (d >> 1);
                        g_Kh[idx] = pack2(vx, vy);
                    } else {
                        __half hx = __float2half_rn(vx);
                        __half hy = __float2half_rn(vy);
                        size_t ix = (((size_t)bhh * 64 + d) * 1024 + (t >> 1)) * 2 + (t & 1);
                        __half* Vh = reinterpret_cast<__half*>(g_Vh);
                        Vh[ix] = hx; Vh[ix + 2048] = hy;   // d+1 -> +1024 u32 = +2048 halfs
                    }
                } else {
                    float2 v; v.x = vx; v.y = vy;
                    *(float2*)&C[(size_t)m * N2 + n] = v;
                }
            }
        }
    }
}

// ================= Attention (1-pass fp16 flash, ldmatrix, 2-stage) ========
#define ATS 36
#define A_VHI 2304
#define A_STAGE 4608
#define ATTN_SMEM (2 * A_STAGE * 4)

__device__ __forceinline__ void a_load_stage(uint32_t sbase, int bh, int base, int tid)
{
#pragma unroll
    for (int j = 0; j < 2; j++) {
        int i = tid + j * 256;
        int r = i >> 3, c = (i & 7) * 4;
        uint32_t off = (r * ATS + c) * 4;
        size_t srcK = ((size_t)bh * T_ + base + r) * 32 + c;
        size_t srcV = ((size_t)bh * 64 + r) * 1024 + (base >> 1) + c;
        cp16(sbase + off,             &g_Kh[srcK]);
        cp16(sbase + A_VHI * 4 + off, &g_Vh[srcV]);
    }
}

__global__ __launch_bounds__(256, 2) void attnb()
{
    extern __shared__ uint32_t sm[];
    const int tid = threadIdx.x, warp = tid >> 5, lane = tid & 31;
    const int g = lane >> 2, tg = lane & 3;
    const int qb = blockIdx.x, bh = blockIdx.y;
    const int wrow = warp * 16;
    const int qr0  = qb * 128 + wrow;

    const uint32_t sbase = sptr(sm);
    const int f_row = ((lane >> 4) & 1) * 8 + (lane & 7);
    const int f_col = ((lane >> 3) & 1) * 4;

    uint32_t qfh[4][4];
    {
        size_t r0 = ((size_t)bh * T_ + qr0 + g) * 32;
        size_t r8 = r0 + 8 * 32;
#pragma unroll
        for (int ka = 0; ka < 4; ka++) {
            int kp = ka * 8 + tg;
            qfh[ka][0] = g_Qh[r0 + kp];
            qfh[ka][1] = g_Qh[r8 + kp];
            qfh[ka][2] = g_Qh[r0 + kp + 4];
            qfh[ka][3] = g_Qh[r8 + kp + 4];
        }
    }

    float of[8][4];
#pragma unroll
    for (int j = 0; j < 8; j++)
#pragma unroll
        for (int r = 0; r < 4; r++) of[j][r] = 0.f;

    const float NEG_INF = __int_as_float(0xff800000);
    float mrow[2] = {NEG_INF, NEG_INF};
    float lrow[2] = {0.f, 0.f};

    const int ntiles = 2 * qb + 2;
    a_load_stage(sbase, bh, 0, tid);
    CP_COMMIT();

    for (int kt = 0; kt < ntiles; kt++) {
        const int base = kt * 64;
        __syncthreads();
        if (kt + 1 < ntiles)
            a_load_stage(sbase + ((kt + 1) & 1) * (A_STAGE * 4), bh, base + 64, tid);
        CP_COMMIT();
        CP_WAIT1();
        __syncthreads();

        if (base > qr0 + 15) continue;
        const uint32_t st = sbase + (kt & 1) * (A_STAGE * 4);

        // ---- S = Q K^T (1-pass) ----
        float sacc[8][4];
#pragma unroll
        for (int j = 0; j < 8; j++)
#pragma unroll
            for (int r = 0; r < 4; r++) sacc[j][r] = 0.f;

#pragma unroll
        for (int nb = 0; nb < 4; nb++) {
#pragma unroll
            for (int ka = 0; ka < 4; ka++) {
                uint32_t off = ((f_row + nb * 16) * ATS + ka * 8 + f_col) * 4;
                uint32_t kh4[4];
                ldsm4(kh4, st + off);
                mma16(sacc[2 * nb],     qfh[ka], &kh4[0]);
                mma16(sacc[2 * nb + 1], qfh[ka], &kh4[2]);
            }
        }

        // ---- causal mask ----
        if (base + 63 > qr0) {
#pragma unroll
            for (int na = 0; na < 8; na++)
#pragma unroll
                for (int r = 0; r < 4; r++) {
                    int q = qr0 + g + (r >> 1) * 8;
                    int j = base + na * 8 + tg * 2 + (r & 1);
                    if (j > q) sacc[na][r] = NEG_INF;
                }
        }

        // ---- online softmax ----
#pragma unroll
        for (int h = 0; h < 2; h++) {
            float rm = NEG_INF;
#pragma unroll
            for (int na = 0; na < 8; na++) {
                rm = fmaxf(rm, sacc[na][h * 2 + 0]);
                rm = fmaxf(rm, sacc[na][h * 2 + 1]);
            }
            rm = fmaxf(rm, __shfl_xor_sync(0xffffffffu, rm, 1));
            rm = fmaxf(rm, __shfl_xor_sync(0xffffffffu, rm, 2));
            float mn   = fmaxf(mrow[h], rm);
            float corr = __expf(mrow[h] - mn);
            mrow[h] = mn;
            float sum = 0.f;
#pragma unroll
            for (int na = 0; na < 8; na++) {
                float p0 = __expf(sacc[na][h * 2 + 0] - mn);
                float p1 = __expf(sacc[na][h * 2 + 1] - mn);
                sacc[na][h * 2 + 0] = p0;
                sacc[na][h * 2 + 1] = p1;
                sum += p0 + p1;
            }
            sum += __shfl_xor_sync(0xffffffffu, sum, 1);
            sum += __shfl_xor_sync(0xffffffffu, sum, 2);
            lrow[h] = lrow[h] * corr + sum;
#pragma unroll
            for (int na = 0; na < 8; na++) {
                of[na][h * 2 + 0] *= corr;
                of[na][h * 2 + 1] *= corr;
            }
        }

        // ---- O += P V ----
#pragma unroll
        for (int ka = 0; ka < 4; ka++) {
            uint32_t pah[4];
            pah[0] = pack2(sacc[2 * ka][0],     sacc[2 * ka][1]);
            pah[1] = pack2(sacc[2 * ka][2],     sacc[2 * ka][3]);
            pah[2] = pack2(sacc[2 * ka + 1][0], sacc[2 * ka + 1][1]);
            pah[3] = pack2(sacc[2 * ka + 1][2], sacc[2 * ka + 1][3]);
#pragma unroll
            for (int nb = 0; nb < 4; nb++) {
                uint32_t off = ((f_row + nb * 16) * ATS + ka * 8 + f_col) * 4;
                uint32_t vh4[4];
                ldsm4(vh4, st + A_VHI * 4 + off);
                mma16(of[2 * nb],     pah, &vh4[0]);
                mma16(of[2 * nb + 1], pah, &vh4[2]);
            }
        }
    }

    // ---- finalize ----
    const int bb = bh >> 4, hh = bh & 15;
    float inv0 = 1.f / lrow[0];
    float inv1 = 1.f / lrow[1];
    int q = qb * 128 + wrow + g;
    size_t r0 = (size_t)(bb * T_ + q) * 512 + hh * 32;
    size_t r8 = r0 + 8 * 512;
#pragma unroll
    for (int na = 0; na < 8; na++) {
        int dp = (na * 8 + tg * 2) >> 1;
        g_Oh[r0 + dp] = pack2(of[na][0] * inv0, of[na][1] * inv0);
        g_Oh[r8 + dp] = pack2(of[na][2] * inv1, of[na][3] * inv1);
    }
}

// ---------------- launch ----------------
extern "C" void kernel_launch(void* const* d_in, const int* in_sizes, int n_in,
                              void* d_out, int out_size)
{
    const float* x    = (const float*)d_in[0];
    const float* Wqkv = (const float*)d_in[1];
    const float* bqkv = (const float*)d_in[2];
    const float* Wout = (const float*)d_in[3];
    const float* bout = (const float*)d_in[4];
    float* out = (float*)d_out;

    static bool attr_done = false;
    if (!attr_done) {
        cudaFuncSetAttribute((void*)gemmb<0>, cudaFuncAttributeMaxDynamicSharedMemorySize, GEMM_SMEM);
        cudaFuncSetAttribute((void*)gemmb<1>, cudaFuncAttributeMaxDynamicSharedMemorySize, GEMM_SMEM);
        cudaFuncSetAttribute((void*)attnb,    cudaFuncAttributeMaxDynamicSharedMemorySize, ATTN_SMEM);
        attr_done = true;
    }

    prep_all<<<9216, 256>>>(x, Wqkv, Wout);

    dim3 g1(N1 / 128, M_ / 128);   // (24, 32)
    gemmb<0><<<g1, 128, GEMM_SMEM>>>(bqkv, nullptr);

    dim3 ga(T_ / 128, B_ * H_);    // (16, 32)
    attnb<<<ga, 256, ATTN_SMEM>>>();

    dim3 g2(N2 / 128, M_ / 128);   // (8, 32)
    gemmb<1><<<g2, 128, GEMM_SMEM>>>(bout, out);
}

// round 13
// speedup vs baseline: 1.0025x; 1.0025x over previous
#include <cuda_runtime.h>
#include <cuda_fp16.h>
#include <math.h>
#include <stdint.h>

#define B_  2
#define T_  2048
#define EMB 1024
#define H_  16
#define D_  64
#define M_  (B_ * T_)          // 4096
#define N1  3072
#define N2  1024
#define SCALE_LOG2E 0.1803368801111204f   // 0.125 * log2(e)

// ---------------- scratch (u32 = fp16x2, hi-only) ----------------
__device__ uint32_t g_xh[4096 * 512];        // x  [m][kpair]
__device__ uint32_t g_wqh[3072 * 512];       // Wqkv^T [n][kpair]
__device__ uint32_t g_woh[1024 * 512];       // Wout^T [n][kpair]
__device__ uint32_t g_Qh[2097152];           // [bh][t][32 dpair], pre-scaled by SCALE*log2e
__device__ uint32_t g_Kh[2097152];           // [bh][t][32 dpair]
__device__ uint32_t g_Vh[2097152];           // [bh][64 d][1024 tpair]
__device__ uint32_t g_Oh[2097152];           // [m][512 kpair]

// ---------------- helpers ----------------
__device__ __forceinline__ uint32_t pack2(float x, float y) {   // low=x, high=y
    uint32_t r;
    asm("cvt.rn.f16x2.f32 %0, %1, %2;" : "=r"(r) : "f"(y), "f"(x));
    return r;
}
__device__ __forceinline__ void mma16(float* c, const uint32_t* a, const uint32_t* b) {
    asm volatile(
        "mma.sync.aligned.m16n8k16.row.col.f32.f16.f16.f32 "
        "{%0,%1,%2,%3},{%4,%5,%6,%7},{%8,%9},{%0,%1,%2,%3};\n"
        : "+f"(c[0]), "+f"(c[1]), "+f"(c[2]), "+f"(c[3])
        : "r"(a[0]), "r"(a[1]), "r"(a[2]), "r"(a[3]), "r"(b[0]), "r"(b[1]));
}
__device__ __forceinline__ void ldsm4(uint32_t* r, uint32_t saddr) {
    asm volatile("ldmatrix.sync.aligned.m8n8.x4.shared.b16 {%0,%1,%2,%3}, [%4];"
                 : "=r"(r[0]), "=r"(r[1]), "=r"(r[2]), "=r"(r[3]) : "r"(saddr));
}
__device__ __forceinline__ uint32_t sptr(const void* p) {
    return (uint32_t)__cvta_generic_to_shared(p);
}
__device__ __forceinline__ void cp16(uint32_t saddr, const void* g) {
    asm volatile("cp.async.cg.shared.global [%0], [%1], 16;\n" :: "r"(saddr), "l"(g));
}
#define CP_COMMIT() asm volatile("cp.async.commit_group;\n" ::)
#define CP_WAIT1()  asm volatile("cp.async.wait_group 1;\n" ::)
#define CP_WAIT2()  asm volatile("cp.async.wait_group 2;\n" ::)

// ---------------- merged prep kernel ----------------
__global__ __launch_bounds__(256) void prep_all(const float* __restrict__ x,
                                                const float* __restrict__ Wqkv,
                                                const float* __restrict__ Wout)
{
    __shared__ uint32_t sh[64][33];
    const int tid = threadIdx.x;
    const int bid = blockIdx.x;

    if (bid < 8192) {
        int i = bid * 256 + tid;
        float2 v = ((const float2*)x)[i];
        g_xh[i] = pack2(v.x, v.y);
        return;
    }
    const float* W;
    uint32_t* Dh;
    int N, n0, kp0;
    if (bid < 8960) {
        int b2 = bid - 8192;            // (48, 16)
        W = Wqkv; Dh = g_wqh; N = N1;
        n0 = (b2 % 48) * 64;  kp0 = (b2 / 48) * 32;
    } else {
        int b3 = bid - 8960;            // (16, 16)
        W = Wout; Dh = g_woh; N = N2;
        n0 = (b3 % 16) * 64;  kp0 = (b3 / 16) * 32;
    }
#pragma unroll
    for (int r = 0; r < 8; r++) {
        int kp = r * 4 + (tid >> 6);
        int n  = tid & 63;
        float a = W[(size_t)(2 * (kp0 + kp))     * N + n0 + n];
        float b = W[(size_t)(2 * (kp0 + kp) + 1) * N + n0 + n];
        sh[n][kp] = pack2(a, b);
    }
    __syncthreads();
#pragma unroll
    for (int w = 0; w < 8; w++) {
        int n = w * 8 + (tid >> 5), c = tid & 31;
        Dh[(size_t)(n0 + n) * 512 + kp0 + c] = sh[n][c];
    }
}

// ================= GEMM (1-pass fp16, 8 warps 64x32, 3-stage cp.async) =====
#define GS 20
#define G_BHI 2560
#define G_STAGE 5120
#define GEMM_SMEM (3 * G_STAGE * 4)

__device__ __forceinline__ void g_load_stage(uint32_t sbase, int kb, int bm, int bn, int tid,
                                             const uint32_t* __restrict__ Ah,
                                             const uint32_t* __restrict__ Wh)
{
#pragma unroll
    for (int j = 0; j < 2; j++) {
        int idx = tid + j * 256;
        int row = idx >> 2, c = (idx & 3) * 4;
        size_t srcA = (size_t)(bm + row) * 512 + kb * 16 + c;
        size_t srcB = (size_t)(bn + row) * 512 + kb * 16 + c;
        uint32_t off = (row * GS + c) * 4;
        cp16(sbase + off,             &Ah[srcA]);
        cp16(sbase + G_BHI * 4 + off, &Wh[srcB]);
    }
}

template<int MODE>
__global__ __launch_bounds__(256, 2) void gemmb(const float* __restrict__ bias,
                                                float* __restrict__ C)
{
    extern __shared__ uint32_t smem_g[];
    const uint32_t* Ah = (MODE == 0) ? g_xh  : g_Oh;
    const uint32_t* Wh = (MODE == 0) ? g_wqh : g_woh;

    const int tid  = threadIdx.x;
    const int warp = tid >> 5, lane = tid & 31;
    const int g    = lane >> 2, tg = lane & 3;
    const int wy   = warp >> 2, wx = warp & 3;      // 2 x 4
    const int bm   = blockIdx.y * 128, bn = blockIdx.x * 128;

    float acc[4][4][4];
#pragma unroll
    for (int i = 0; i < 4; i++)
#pragma unroll
        for (int j = 0; j < 4; j++)
#pragma unroll
            for (int r = 0; r < 4; r++) acc[i][j][r] = 0.f;

    const uint32_t sbase = sptr(smem_g);
    const int a_row = wy * 64 + (lane & 15);
    const int a_col = (lane >> 4) * 4;
    const int b_row = wx * 32 + ((lane >> 4) & 1) * 8 + (lane & 7);
    const int b_col = ((lane >> 3) & 1) * 4;

    g_load_stage(sbase,                 0, bm, bn, tid, Ah, Wh); CP_COMMIT();
    g_load_stage(sbase + G_STAGE * 4,   1, bm, bn, tid, Ah, Wh); CP_COMMIT();
    g_load_stage(sbase + G_STAGE * 8,   2, bm, bn, tid, Ah, Wh); CP_COMMIT();

    int s = 0;
    for (int kb = 0; kb < 32; kb++) {
        CP_WAIT2();
        __syncthreads();
        const uint32_t st = sbase + s * (G_STAGE * 4);

#pragma unroll
        for (int ka = 0; ka < 2; ka++) {
            uint32_t kbh[2][4];
#pragma unroll
            for (int nb = 0; nb < 2; nb++) {
                uint32_t off = ((b_row + nb * 16) * GS + ka * 8 + b_col) * 4;
                ldsm4(kbh[nb], st + G_BHI * 4 + off);
            }
#pragma unroll
            for (int ma = 0; ma < 4; ma++) {
                uint32_t off = ((a_row + ma * 16) * GS + ka * 8 + a_col) * 4;
                uint32_t ah[4];
                ldsm4(ah, st + off);
#pragma unroll
                for (int na = 0; na < 4; na++)
                    mma16(acc[ma][na], ah, &kbh[na >> 1][(na & 1) * 2]);
            }
        }
        __syncthreads();
        if (kb + 3 < 32)
            g_load_stage(st, kb + 3, bm, bn, tid, Ah, Wh);
        CP_COMMIT();
        s = (s == 2) ? 0 : s + 1;
    }

    // ---------- epilogue ----------
#pragma unroll
    for (int ma = 0; ma < 4; ma++) {
        int m0 = bm + wy * 64 + ma * 16 + g;
#pragma unroll
        for (int na = 0; na < 4; na++) {
            int n = bn + wx * 32 + na * 8 + tg * 2;
            float b0v = bias[n], b1v = bias[n + 1];
#pragma unroll
            for (int half = 0; half < 2; half++) {
                int m = m0 + half * 8;
                float vx = acc[ma][na][half * 2 + 0] + b0v;
                float vy = acc[ma][na][half * 2 + 1] + b1v;
                if (MODE == 0) {
                    int bb2 = m >> 11, t = m & (T_ - 1);
                    int sec = n >> 10, rem = n & 1023;
                    int h = rem >> 6, d = rem & 63;
                    int bhh = bb2 * H_ + h;
                    if (sec == 0) {
                        size_t idx = ((size_t)bhh * T_ + t) * 32 + (d >> 1);
                        g_Qh[idx] = pack2(vx * SCALE_LOG2E, vy * SCALE_LOG2E);
                    } else if (sec == 1) {
                        size_t idx = ((size_t)bhh * T_ + t) * 32 + (d >> 1);
                        g_Kh[idx] = pack2(vx, vy);
                    } else {
                        __half hx = __float2half_rn(vx);
                        __half hy = __float2half_rn(vy);
                        size_t ix = (((size_t)bhh * 64 + d) * 1024 + (t >> 1)) * 2 + (t & 1);
                        __half* Vh = reinterpret_cast<__half*>(g_Vh);
                        Vh[ix] = hx; Vh[ix + 2048] = hy;
                    }
                } else {
                    float2 v; v.x = vx; v.y = vy;
                    *(float2*)&C[(size_t)m * N2 + n] = v;
                }
            }
        }
    }
}

// ================= Attention (1-pass fp16 flash, exp2 softmax) =============
#define ATS 36
#define A_VHI 2304
#define A_STAGE 4608
#define ATTN_SMEM (2 * A_STAGE * 4)

__device__ __forceinline__ void a_load_stage(uint32_t sbase, int bh, int base, int tid)
{
#pragma unroll
    for (int j = 0; j < 2; j++) {
        int i = tid + j * 256;
        int r = i >> 3, c = (i & 7) * 4;
        uint32_t off = (r * ATS + c) * 4;
        size_t srcK = ((size_t)bh * T_ + base + r) * 32 + c;
        size_t srcV = ((size_t)bh * 64 + r) * 1024 + (base >> 1) + c;
        cp16(sbase + off,             &g_Kh[srcK]);
        cp16(sbase + A_VHI * 4 + off, &g_Vh[srcV]);
    }
}

__global__ __launch_bounds__(256, 2) void attnb()
{
    extern __shared__ uint32_t sm[];
    const int tid = threadIdx.x, warp = tid >> 5, lane = tid & 31;
    const int g = lane >> 2, tg = lane & 3;
    const int qb = gridDim.x - 1 - blockIdx.x;      // heavy tiles first
    const int bh = blockIdx.y;
    const int wrow = warp * 16;
    const int qr0  = qb * 128 + wrow;

    const uint32_t sbase = sptr(sm);
    const int f_row = ((lane >> 4) & 1) * 8 + (lane & 7);
    const int f_col = ((lane >> 3) & 1) * 4;

    uint32_t qfh[4][4];
    {
        size_t r0 = ((size_t)bh * T_ + qr0 + g) * 32;
        size_t r8 = r0 + 8 * 32;
#pragma unroll
        for (int ka = 0; ka < 4; ka++) {
            int kp = ka * 8 + tg;
            qfh[ka][0] = g_Qh[r0 + kp];
            qfh[ka][1] = g_Qh[r8 + kp];
            qfh[ka][2] = g_Qh[r0 + kp + 4];
            qfh[ka][3] = g_Qh[r8 + kp + 4];
        }
    }

    float of[8][4];
#pragma unroll
    for (int j = 0; j < 8; j++)
#pragma unroll
        for (int r = 0; r < 4; r++) of[j][r] = 0.f;

    const float NEG_INF = __int_as_float(0xff800000);
    float mrow[2] = {NEG_INF, NEG_INF};
    float lrow[2] = {0.f, 0.f};

    const int ntiles = 2 * qb + 2;
    a_load_stage(sbase, bh, 0, tid);
    CP_COMMIT();

    for (int kt = 0; kt < ntiles; kt++) {
        const int base = kt * 64;
        __syncthreads();
        if (kt + 1 < ntiles)
            a_load_stage(sbase + ((kt + 1) & 1) * (A_STAGE * 4), bh, base + 64, tid);
        CP_COMMIT();
        CP_WAIT1();
        __syncthreads();

        if (base > qr0 + 15) continue;
        const uint32_t st = sbase + (kt & 1) * (A_STAGE * 4);

        // ---- S = Q K^T (scores pre-scaled to log2 domain) ----
        float sacc[8][4];
#pragma unroll
        for (int j = 0; j < 8; j++)
#pragma unroll
            for (int r = 0; r < 4; r++) sacc[j][r] = 0.f;

#pragma unroll
        for (int nb = 0; nb < 4; nb++) {
#pragma unroll
            for (int ka = 0; ka < 4; ka++) {
                uint32_t off = ((f_row + nb * 16) * ATS + ka * 8 + f_col) * 4;
                uint32_t kh4[4];
                ldsm4(kh4, st + off);
                mma16(sacc[2 * nb],     qfh[ka], &kh4[0]);
                mma16(sacc[2 * nb + 1], qfh[ka], &kh4[2]);
            }
        }

        // ---- causal mask ----
        if (base + 63 > qr0) {
#pragma unroll
            for (int na = 0; na < 8; na++)
#pragma unroll
                for (int r = 0; r < 4; r++) {
                    int q = qr0 + g + (r >> 1) * 8;
                    int j = base + na * 8 + tg * 2 + (r & 1);
                    if (j > q) sacc[na][r] = NEG_INF;
                }
        }

        // ---- online softmax (base-2) ----
#pragma unroll
        for (int h = 0; h < 2; h++) {
            float rm = NEG_INF;
#pragma unroll
            for (int na = 0; na < 8; na++) {
                rm = fmaxf(rm, sacc[na][h * 2 + 0]);
                rm = fmaxf(rm, sacc[na][h * 2 + 1]);
            }
            rm = fmaxf(rm, __shfl_xor_sync(0xffffffffu, rm, 1));
            rm = fmaxf(rm, __shfl_xor_sync(0xffffffffu, rm, 2));
            float mn   = fmaxf(mrow[h], rm);
            float corr = exp2f(mrow[h] - mn);
            mrow[h] = mn;
            float sum = 0.f;
#pragma unroll
            for (int na = 0; na < 8; na++) {
                float p0 = exp2f(sacc[na][h * 2 + 0] - mn);
                float p1 = exp2f(sacc[na][h * 2 + 1] - mn);
                sacc[na][h * 2 + 0] = p0;
                sacc[na][h * 2 + 1] = p1;
                sum += p0 + p1;
            }
            sum += __shfl_xor_sync(0xffffffffu, sum, 1);
            sum += __shfl_xor_sync(0xffffffffu, sum, 2);
            lrow[h] = lrow[h] * corr + sum;
#pragma unroll
            for (int na = 0; na < 8; na++) {
                of[na][h * 2 + 0] *= corr;
                of[na][h * 2 + 1] *= corr;
            }
        }

        // ---- O += P V ----
#pragma unroll
        for (int ka = 0; ka < 4; ka++) {
            uint32_t pah[4];
            pah[0] = pack2(sacc[2 * ka][0],     sacc[2 * ka][1]);
            pah[1] = pack2(sacc[2 * ka][2],     sacc[2 * ka][3]);
            pah[2] = pack2(sacc[2 * ka + 1][0], sacc[2 * ka + 1][1]);
            pah[3] = pack2(sacc[2 * ka + 1][2], sacc[2 * ka + 1][3]);
#pragma unroll
            for (int nb = 0; nb < 4; nb++) {
                uint32_t off = ((f_row + nb * 16) * ATS + ka * 8 + f_col) * 4;
                uint32_t vh4[4];
                ldsm4(vh4, st + A_VHI * 4 + off);
                mma16(of[2 * nb],     pah, &vh4[0]);
                mma16(of[2 * nb + 1], pah, &vh4[2]);
            }
        }
    }

    // ---- finalize ----
    const int bb = bh >> 4, hh = bh & 15;
    float inv0 = 1.f / lrow[0];
    float inv1 = 1.f / lrow[1];
    int q = qb * 128 + wrow + g;
    size_t r0 = (size_t)(bb * T_ + q) * 512 + hh * 32;
    size_t r8 = r0 + 8 * 512;
#pragma unroll
    for (int na = 0; na < 8; na++) {
        int dp = (na * 8 + tg * 2) >> 1;
        g_Oh[r0 + dp] = pack2(of[na][0] * inv0, of[na][1] * inv0);
        g_Oh[r8 + dp] = pack2(of[na][2] * inv1, of[na][3] * inv1);
    }
}

// ---------------- launch ----------------
extern "C" void kernel_launch(void* const* d_in, const int* in_sizes, int n_in,
                              void* d_out, int out_size)
{
    const float* x    = (const float*)d_in[0];
    const float* Wqkv = (const float*)d_in[1];
    const float* bqkv = (const float*)d_in[2];
    const float* Wout = (const float*)d_in[3];
    const float* bout = (const float*)d_in[4];
    float* out = (float*)d_out;

    static bool attr_done = false;
    if (!attr_done) {
        cudaFuncSetAttribute((void*)gemmb<0>, cudaFuncAttributeMaxDynamicSharedMemorySize, GEMM_SMEM);
        cudaFuncSetAttribute((void*)gemmb<1>, cudaFuncAttributeMaxDynamicSharedMemorySize, GEMM_SMEM);
        cudaFuncSetAttribute((void*)attnb,    cudaFuncAttributeMaxDynamicSharedMemorySize, ATTN_SMEM);
        attr_done = true;
    }

    prep_all<<<9216, 256>>>(x, Wqkv, Wout);

    dim3 g1(N1 / 128, M_ / 128);   // (24, 32)
    gemmb<0><<<g1, 256, GEMM_SMEM>>>(bqkv, nullptr);

    dim3 ga(T_ / 128, B_ * H_);    // (16, 32)
    attnb<<<ga, 256, ATTN_SMEM>>>();

    dim3 g2(N2 / 128, M_ / 128);   // (8, 32)
    gemmb<1><<<g2, 256, GEMM_SMEM>>>(bout, out);
}

// round 14
// speedup vs baseline: 1.0296x; 1.0270x over previous
#include <cuda_runtime.h>
#include <cuda_fp16.h>
#include <math.h>
#include <stdint.h>

#define B_  2
#define T_  2048
#define EMB 1024
#define H_  16
#define D_  64
#define M_  (B_ * T_)          // 4096
#define N1  3072
#define N2  1024
#define SCALE_LOG2E 0.1803368801111204f   // 0.125 * log2(e)

// ---------------- scratch (u32 = fp16x2, hi-only) ----------------
__device__ uint32_t g_xh[4096 * 512];        // x  [m][kpair]
__device__ uint32_t g_wqh[3072 * 512];       // Wqkv^T [n][kpair]
__device__ uint32_t g_woh[1024 * 512];       // Wout^T [n][kpair]
__device__ uint32_t g_Qh[2097152];           // [bh][t][32 dpair], pre-scaled
__device__ uint32_t g_Kh[2097152];           // [bh][t][32 dpair]
__device__ uint32_t g_Vh[2097152];           // [bh][64 d][1024 tpair]
__device__ uint32_t g_Oh[2097152];           // [m][512 kpair]

// ---------------- helpers ----------------
__device__ __forceinline__ uint32_t pack2(float x, float y) {   // low=x, high=y
    uint32_t r;
    asm("cvt.rn.f16x2.f32 %0, %1, %2;" : "=r"(r) : "f"(y), "f"(x));
    return r;
}
__device__ __forceinline__ void mma16(float* c, const uint32_t* a, const uint32_t* b) {
    asm volatile(
        "mma.sync.aligned.m16n8k16.row.col.f32.f16.f16.f32 "
        "{%0,%1,%2,%3},{%4,%5,%6,%7},{%8,%9},{%0,%1,%2,%3};\n"
        : "+f"(c[0]), "+f"(c[1]), "+f"(c[2]), "+f"(c[3])
        : "r"(a[0]), "r"(a[1]), "r"(a[2]), "r"(a[3]), "r"(b[0]), "r"(b[1]));
}
__device__ __forceinline__ void ldsm4(uint32_t* r, uint32_t saddr) {
    asm volatile("ldmatrix.sync.aligned.m8n8.x4.shared.b16 {%0,%1,%2,%3}, [%4];"
                 : "=r"(r[0]), "=r"(r[1]), "=r"(r[2]), "=r"(r[3]) : "r"(saddr));
}
__device__ __forceinline__ uint32_t sptr(const void* p) {
    return (uint32_t)__cvta_generic_to_shared(p);
}
__device__ __forceinline__ void cp16(uint32_t saddr, const void* g) {
    asm volatile("cp.async.cg.shared.global [%0], [%1], 16;\n" :: "r"(saddr), "l"(g));
}
#define CP_COMMIT() asm volatile("cp.async.commit_group;\n" ::)
#define CP_WAIT1()  asm volatile("cp.async.wait_group 1;\n" ::)

// ---------------- merged prep kernel ----------------
__global__ __launch_bounds__(256) void prep_all(const float* __restrict__ x,
                                                const float* __restrict__ Wqkv,
                                                const float* __restrict__ Wout)
{
    __shared__ uint32_t sh[64][33];
    const int tid = threadIdx.x;
    const int bid = blockIdx.x;

    if (bid < 8192) {
        int i = bid * 256 + tid;
        float2 v = ((const float2*)x)[i];
        g_xh[i] = pack2(v.x, v.y);
        return;
    }
    const float* W;
    uint32_t* Dh;
    int N, n0, kp0;
    if (bid < 8960) {
        int b2 = bid - 8192;
        W = Wqkv; Dh = g_wqh; N = N1;
        n0 = (b2 % 48) * 64;  kp0 = (b2 / 48) * 32;
    } else {
        int b3 = bid - 8960;
        W = Wout; Dh = g_woh; N = N2;
        n0 = (b3 % 16) * 64;  kp0 = (b3 / 16) * 32;
    }
#pragma unroll
    for (int r = 0; r < 8; r++) {
        int kp = r * 4 + (tid >> 6);
        int n  = tid & 63;
        float a = W[(size_t)(2 * (kp0 + kp))     * N + n0 + n];
        float b = W[(size_t)(2 * (kp0 + kp) + 1) * N + n0 + n];
        sh[n][kp] = pack2(a, b);
    }
    __syncthreads();
#pragma unroll
    for (int w = 0; w < 8; w++) {
        int n = w * 8 + (tid >> 5), c = tid & 31;
        Dh[(size_t)(n0 + n) * 512 + kp0 + c] = sh[n][c];
    }
}

// ================= GEMM: 3-stage, load-2-ahead, SINGLE sync per k-block ====
#define GS 20
#define G_BHI 2560
#define G_STAGE 5120
#define GEMM_SMEM (3 * G_STAGE * 4)

__device__ __forceinline__ void g_load_stage(uint32_t sbase, int kb, int bm, int bn, int tid,
                                             const uint32_t* __restrict__ Ah,
                                             const uint32_t* __restrict__ Wh)
{
#pragma unroll
    for (int j = 0; j < 2; j++) {
        int idx = tid + j * 256;
        int row = idx >> 2, c = (idx & 3) * 4;
        size_t srcA = (size_t)(bm + row) * 512 + kb * 16 + c;
        size_t srcB = (size_t)(bn + row) * 512 + kb * 16 + c;
        uint32_t off = (row * GS + c) * 4;
        cp16(sbase + off,             &Ah[srcA]);
        cp16(sbase + G_BHI * 4 + off, &Wh[srcB]);
    }
}

template<int MODE>
__global__ __launch_bounds__(256, 2) void gemmb(const float* __restrict__ bias,
                                                float* __restrict__ C)
{
    extern __shared__ uint32_t smem_g[];
    const uint32_t* Ah = (MODE == 0) ? g_xh  : g_Oh;
    const uint32_t* Wh = (MODE == 0) ? g_wqh : g_woh;

    const int tid  = threadIdx.x;
    const int warp = tid >> 5, lane = tid & 31;
    const int g    = lane >> 2, tg = lane & 3;
    const int wy   = warp >> 2, wx = warp & 3;      // 2 x 4
    const int bm   = blockIdx.y * 128, bn = blockIdx.x * 128;

    float acc[4][4][4];
#pragma unroll
    for (int i = 0; i < 4; i++)
#pragma unroll
        for (int j = 0; j < 4; j++)
#pragma unroll
            for (int r = 0; r < 4; r++) acc[i][j][r] = 0.f;

    const uint32_t sbase = sptr(smem_g);
    const int a_row = wy * 64 + (lane & 15);
    const int a_col = (lane >> 4) * 4;
    const int b_row = wx * 32 + ((lane >> 4) & 1) * 8 + (lane & 7);
    const int b_col = ((lane >> 3) & 1) * 4;

    g_load_stage(sbase,               0, bm, bn, tid, Ah, Wh); CP_COMMIT();
    g_load_stage(sbase + G_STAGE * 4, 1, bm, bn, tid, Ah, Wh); CP_COMMIT();

    int sr = 0, sw = 2;   // read stage of kb, write stage of kb+2
    for (int kb = 0; kb < 32; kb++) {
        CP_WAIT1();                 // group kb complete (1 newer may be pending)
        __syncthreads();            // everyone done reading stage sw (= kb-1's read... kb+2's target)
        if (kb + 2 < 32)
            g_load_stage(sbase + sw * (G_STAGE * 4), kb + 2, bm, bn, tid, Ah, Wh);
        CP_COMMIT();
        const uint32_t st = sbase + sr * (G_STAGE * 4);

#pragma unroll
        for (int ka = 0; ka < 2; ka++) {
            uint32_t kbh[2][4];
#pragma unroll
            for (int nb = 0; nb < 2; nb++) {
                uint32_t off = ((b_row + nb * 16) * GS + ka * 8 + b_col) * 4;
                ldsm4(kbh[nb], st + G_BHI * 4 + off);
            }
#pragma unroll
            for (int ma = 0; ma < 4; ma++) {
                uint32_t off = ((a_row + ma * 16) * GS + ka * 8 + a_col) * 4;
                uint32_t ah[4];
                ldsm4(ah, st + off);
#pragma unroll
                for (int na = 0; na < 4; na++)
                    mma16(acc[ma][na], ah, &kbh[na >> 1][(na & 1) * 2]);
            }
        }
        sr = (sr == 2) ? 0 : sr + 1;
        sw = (sw == 2) ? 0 : sw + 1;
    }

    // ---------- epilogue ----------
#pragma unroll
    for (int ma = 0; ma < 4; ma++) {
        int m0 = bm + wy * 64 + ma * 16 + g;
#pragma unroll
        for (int na = 0; na < 4; na++) {
            int n = bn + wx * 32 + na * 8 + tg * 2;
            float b0v = bias[n], b1v = bias[n + 1];
#pragma unroll
            for (int half = 0; half < 2; half++) {
                int m = m0 + half * 8;
                float vx = acc[ma][na][half * 2 + 0] + b0v;
                float vy = acc[ma][na][half * 2 + 1] + b1v;
                if (MODE == 0) {
                    int bb2 = m >> 11, t = m & (T_ - 1);
                    int sec = n >> 10, rem = n & 1023;
                    int h = rem >> 6, d = rem & 63;
                    int bhh = bb2 * H_ + h;
                    if (sec == 0) {
                        size_t idx = ((size_t)bhh * T_ + t) * 32 + (d >> 1);
                        g_Qh[idx] = pack2(vx * SCALE_LOG2E, vy * SCALE_LOG2E);
                    } else if (sec == 1) {
                        size_t idx = ((size_t)bhh * T_ + t) * 32 + (d >> 1);
                        g_Kh[idx] = pack2(vx, vy);
                    } else {
                        __half hx = __float2half_rn(vx);
                        __half hy = __float2half_rn(vy);
                        size_t ix = (((size_t)bhh * 64 + d) * 1024 + (t >> 1)) * 2 + (t & 1);
                        __half* Vh = reinterpret_cast<__half*>(g_Vh);
                        Vh[ix] = hx; Vh[ix + 2048] = hy;
                    }
                } else {
                    float2 v; v.x = vx; v.y = vy;
                    *(float2*)&C[(size_t)m * N2 + n] = v;
                }
            }
        }
    }
}

// ============ Attention: 3-stage, load-2-ahead, SINGLE sync per tile =======
#define ATS 36
#define A_VHI 2304
#define A_STAGE 4608
#define ATTN_SMEM (3 * A_STAGE * 4)

__device__ __forceinline__ void a_load_stage(uint32_t sbase, int bh, int base, int tid)
{
#pragma unroll
    for (int j = 0; j < 2; j++) {
        int i = tid + j * 256;
        int r = i >> 3, c = (i & 7) * 4;
        uint32_t off = (r * ATS + c) * 4;
        size_t srcK = ((size_t)bh * T_ + base + r) * 32 + c;
        size_t srcV = ((size_t)bh * 64 + r) * 1024 + (base >> 1) + c;
        cp16(sbase + off,             &g_Kh[srcK]);
        cp16(sbase + A_VHI * 4 + off, &g_Vh[srcV]);
    }
}

__global__ __launch_bounds__(256, 2) void attnb()
{
    extern __shared__ uint32_t sm[];
    const int tid = threadIdx.x, warp = tid >> 5, lane = tid & 31;
    const int g = lane >> 2, tg = lane & 3;
    const int qb = gridDim.x - 1 - blockIdx.x;      // heavy tiles first
    const int bh = blockIdx.y;
    const int wrow = warp * 16;
    const int qr0  = qb * 128 + wrow;

    const uint32_t sbase = sptr(sm);
    const int f_row = ((lane >> 4) & 1) * 8 + (lane & 7);
    const int f_col = ((lane >> 3) & 1) * 4;

    uint32_t qfh[4][4];
    {
        size_t r0 = ((size_t)bh * T_ + qr0 + g) * 32;
        size_t r8 = r0 + 8 * 32;
#pragma unroll
        for (int ka = 0; ka < 4; ka++) {
            int kp = ka * 8 + tg;
            qfh[ka][0] = g_Qh[r0 + kp];
            qfh[ka][1] = g_Qh[r8 + kp];
            qfh[ka][2] = g_Qh[r0 + kp + 4];
            qfh[ka][3] = g_Qh[r8 + kp + 4];
        }
    }

    float of[8][4];
#pragma unroll
    for (int j = 0; j < 8; j++)
#pragma unroll
        for (int r = 0; r < 4; r++) of[j][r] = 0.f;

    const float NEG_INF = __int_as_float(0xff800000);
    float mrow[2] = {NEG_INF, NEG_INF};
    float lrow[2] = {0.f, 0.f};

    const int ntiles = 2 * qb + 2;     // >= 2 always
    a_load_stage(sbase,               bh, 0,  tid); CP_COMMIT();
    a_load_stage(sbase + A_STAGE * 4, bh, 64, tid); CP_COMMIT();

    int sr = 0, sw = 2;
    for (int kt = 0; kt < ntiles; kt++) {
        const int base = kt * 64;
        CP_WAIT1();
        __syncthreads();
        if (kt + 2 < ntiles)
            a_load_stage(sbase + sw * (A_STAGE * 4), bh, base + 128, tid);
        CP_COMMIT();
        const uint32_t st = sbase + sr * (A_STAGE * 4);
        sr = (sr == 2) ? 0 : sr + 1;
        sw = (sw == 2) ? 0 : sw + 1;

        if (base > qr0 + 15) continue;

        // ---- S = Q K^T (log2 domain) ----
        float sacc[8][4];
#pragma unroll
        for (int j = 0; j < 8; j++)
#pragma unroll
            for (int r = 0; r < 4; r++) sacc[j][r] = 0.f;

#pragma unroll
        for (int nb = 0; nb < 4; nb++) {
#pragma unroll
            for (int ka = 0; ka < 4; ka++) {
                uint32_t off = ((f_row + nb * 16) * ATS + ka * 8 + f_col) * 4;
                uint32_t kh4[4];
                ldsm4(kh4, st + off);
                mma16(sacc[2 * nb],     qfh[ka], &kh4[0]);
                mma16(sacc[2 * nb + 1], qfh[ka], &kh4[2]);
            }
        }

        // ---- causal mask ----
        if (base + 63 > qr0) {
#pragma unroll
            for (int na = 0; na < 8; na++)
#pragma unroll
                for (int r = 0; r < 4; r++) {
                    int q = qr0 + g + (r >> 1) * 8;
                    int j = base + na * 8 + tg * 2 + (r & 1);
                    if (j > q) sacc[na][r] = NEG_INF;
                }
        }

        // ---- online softmax (base-2) ----
#pragma unroll
        for (int h = 0; h < 2; h++) {
            float rm = NEG_INF;
#pragma unroll
            for (int na = 0; na < 8; na++) {
                rm = fmaxf(rm, sacc[na][h * 2 + 0]);
                rm = fmaxf(rm, sacc[na][h * 2 + 1]);
            }
            rm = fmaxf(rm, __shfl_xor_sync(0xffffffffu, rm, 1));
            rm = fmaxf(rm, __shfl_xor_sync(0xffffffffu, rm, 2));
            float mn   = fmaxf(mrow[h], rm);
            float corr = exp2f(mrow[h] - mn);
            mrow[h] = mn;
            float sum = 0.f;
#pragma unroll
            for (int na = 0; na < 8; na++) {
                float p0 = exp2f(sacc[na][h * 2 + 0] - mn);
                float p1 = exp2f(sacc[na][h * 2 + 1] - mn);
                sacc[na][h * 2 + 0] = p0;
                sacc[na][h * 2 + 1] = p1;
                sum += p0 + p1;
            }
            sum += __shfl_xor_sync(0xffffffffu, sum, 1);
            sum += __shfl_xor_sync(0xffffffffu, sum, 2);
            lrow[h] = lrow[h] * corr + sum;
#pragma unroll
            for (int na = 0; na < 8; na++) {
                of[na][h * 2 + 0] *= corr;
                of[na][h * 2 + 1] *= corr;
            }
        }

        // ---- O += P V ----
#pragma unroll
        for (int ka = 0; ka < 4; ka++) {
            uint32_t pah[4];
            pah[0] = pack2(sacc[2 * ka][0],     sacc[2 * ka][1]);
            pah[1] = pack2(sacc[2 * ka][2],     sacc[2 * ka][3]);
            pah[2] = pack2(sacc[2 * ka + 1][0], sacc[2 * ka + 1][1]);
            pah[3] = pack2(sacc[2 * ka + 1][2], sacc[2 * ka + 1][3]);
#pragma unroll
            for (int nb = 0; nb < 4; nb++) {
                uint32_t off = ((f_row + nb * 16) * ATS + ka * 8 + f_col) * 4;
                uint32_t vh4[4];
                ldsm4(vh4, st + A_VHI * 4 + off);
                mma16(of[2 * nb],     pah, &vh4[0]);
                mma16(of[2 * nb + 1], pah, &vh4[2]);
            }
        }
    }

    // ---- finalize ----
    const int bb = bh >> 4, hh = bh & 15;
    float inv0 = 1.f / lrow[0];
    float inv1 = 1.f / lrow[1];
    int q = qb * 128 + wrow + g;
    size_t r0 = (size_t)(bb * T_ + q) * 512 + hh * 32;
    size_t r8 = r0 + 8 * 512;
#pragma unroll
    for (int na = 0; na < 8; na++) {
        int dp = (na * 8 + tg * 2) >> 1;
        g_Oh[r0 + dp] = pack2(of[na][0] * inv0, of[na][1] * inv0);
        g_Oh[r8 + dp] = pack2(of[na][2] * inv1, of[na][3] * inv1);
    }
}

// ---------------- launch ----------------
extern "C" void kernel_launch(void* const* d_in, const int* in_sizes, int n_in,
                              void* d_out, int out_size)
{
    const float* x    = (const float*)d_in[0];
    const float* Wqkv = (const float*)d_in[1];
    const float* bqkv = (const float*)d_in[2];
    const float* Wout = (const float*)d_in[3];
    const float* bout = (const float*)d_in[4];
    float* out = (float*)d_out;

    static bool attr_done = false;
    if (!attr_done) {
        cudaFuncSetAttribute((void*)gemmb<0>, cudaFuncAttributeMaxDynamicSharedMemorySize, GEMM_SMEM);
        cudaFuncSetAttribute((void*)gemmb<1>, cudaFuncAttributeMaxDynamicSharedMemorySize, GEMM_SMEM);
        cudaFuncSetAttribute((void*)attnb,    cudaFuncAttributeMaxDynamicSharedMemorySize, ATTN_SMEM);
        attr_done = true;
    }

    prep_all<<<9216, 256>>>(x, Wqkv, Wout);

    dim3 g1(N1 / 128, M_ / 128);   // (24, 32)
    gemmb<0><<<g1, 256, GEMM_SMEM>>>(bqkv, nullptr);

    dim3 ga(T_ / 128, B_ * H_);    // (16, 32)
    attnb<<<ga, 256, ATTN_SMEM>>>();

    dim3 g2(N2 / 128, M_ / 128);   // (8, 32)
    gemmb<1><<<g2, 256, GEMM_SMEM>>>(bout, out);
}

// round 15
// speedup vs baseline: 1.0354x; 1.0056x over previous
#include <cuda_runtime.h>
#include <cuda_fp16.h>
#include <math.h>
#include <stdint.h>

#define B_  2
#define T_  2048
#define EMB 1024
#define H_  16
#define D_  64
#define M_  (B_ * T_)          // 4096
#define N1  3072
#define N2  1024
#define SCALE_LOG2E 0.1803368801111204f   // 0.125 * log2(e)

// ---------------- scratch (u32 = fp16x2, hi-only) ----------------
__device__ uint32_t g_xh[4096 * 512];        // x  [m][kpair]
__device__ uint32_t g_wqh[3072 * 512];       // Wqkv^T [n][kpair]
__device__ uint32_t g_woh[1024 * 512];       // Wout^T [n][kpair]
__device__ uint32_t g_Qh[2097152];           // [bh][t][32 dpair], pre-scaled
__device__ uint32_t g_Kh[2097152];           // [bh][t][32 dpair]
__device__ uint32_t g_Vh[2097152];           // [bh][64 d][1024 tpair]
__device__ uint32_t g_Oh[2097152];           // [m][512 kpair]

// ---------------- helpers ----------------
__device__ __forceinline__ uint32_t pack2(float x, float y) {   // low=x, high=y
    uint32_t r;
    asm("cvt.rn.f16x2.f32 %0, %1, %2;" : "=r"(r) : "f"(y), "f"(x));
    return r;
}
__device__ __forceinline__ uint32_t ex2_f16x2(uint32_t a) {
    uint32_t r;
    asm("ex2.approx.f16x2 %0, %1;" : "=r"(r) : "r"(a));
    return r;
}
__device__ __forceinline__ void mma16(float* c, const uint32_t* a, const uint32_t* b) {
    asm volatile(
        "mma.sync.aligned.m16n8k16.row.col.f32.f16.f16.f32 "
        "{%0,%1,%2,%3},{%4,%5,%6,%7},{%8,%9},{%0,%1,%2,%3};\n"
        : "+f"(c[0]), "+f"(c[1]), "+f"(c[2]), "+f"(c[3])
        : "r"(a[0]), "r"(a[1]), "r"(a[2]), "r"(a[3]), "r"(b[0]), "r"(b[1]));
}
__device__ __forceinline__ void ldsm4(uint32_t* r, uint32_t saddr) {
    asm volatile("ldmatrix.sync.aligned.m8n8.x4.shared.b16 {%0,%1,%2,%3}, [%4];"
                 : "=r"(r[0]), "=r"(r[1]), "=r"(r[2]), "=r"(r[3]) : "r"(saddr));
}
__device__ __forceinline__ uint32_t sptr(const void* p) {
    return (uint32_t)__cvta_generic_to_shared(p);
}
__device__ __forceinline__ void cp16(uint32_t saddr, const void* g) {
    asm volatile("cp.async.cg.shared.global [%0], [%1], 16;\n" :: "r"(saddr), "l"(g));
}
#define CP_COMMIT() asm volatile("cp.async.commit_group;\n" ::)
#define CP_WAIT1()  asm volatile("cp.async.wait_group 1;\n" ::)

// ---------------- merged prep kernel ----------------
__global__ __launch_bounds__(256) void prep_all(const float* __restrict__ x,
                                                const float* __restrict__ Wqkv,
                                                const float* __restrict__ Wout)
{
    __shared__ uint32_t sh[64][33];
    const int tid = threadIdx.x;
    const int bid = blockIdx.x;

    if (bid < 8192) {
        int i = bid * 256 + tid;
        float2 v = ((const float2*)x)[i];
        g_xh[i] = pack2(v.x, v.y);
        return;
    }
    const float* W;
    uint32_t* Dh;
    int N, n0, kp0;
    if (bid < 8960) {
        int b2 = bid - 8192;
        W = Wqkv; Dh = g_wqh; N = N1;
        n0 = (b2 % 48) * 64;  kp0 = (b2 / 48) * 32;
    } else {
        int b3 = bid - 8960;
        W = Wout; Dh = g_woh; N = N2;
        n0 = (b3 % 16) * 64;  kp0 = (b3 / 16) * 32;
    }
#pragma unroll
    for (int r = 0; r < 8; r++) {
        int kp = r * 4 + (tid >> 6);
        int n  = tid & 63;
        float a = W[(size_t)(2 * (kp0 + kp))     * N + n0 + n];
        float b = W[(size_t)(2 * (kp0 + kp) + 1) * N + n0 + n];
        sh[n][kp] = pack2(a, b);
    }
    __syncthreads();
#pragma unroll
    for (int w = 0; w < 8; w++) {
        int n = w * 8 + (tid >> 5), c = tid & 31;
        Dh[(size_t)(n0 + n) * 512 + kp0 + c] = sh[n][c];
    }
}

// ================= GEMM: 3-stage, load-2-ahead, single sync per k-block ====
#define GS 20
#define G_BHI 2560
#define G_STAGE 5120
#define GEMM_SMEM (3 * G_STAGE * 4)

__device__ __forceinline__ void g_load_stage(uint32_t sbase, int kb, int bm, int bn, int tid,
                                             const uint32_t* __restrict__ Ah,
                                             const uint32_t* __restrict__ Wh)
{
#pragma unroll
    for (int j = 0; j < 2; j++) {
        int idx = tid + j * 256;
        int row = idx >> 2, c = (idx & 3) * 4;
        size_t srcA = (size_t)(bm + row) * 512 + kb * 16 + c;
        size_t srcB = (size_t)(bn + row) * 512 + kb * 16 + c;
        uint32_t off = (row * GS + c) * 4;
        cp16(sbase + off,             &Ah[srcA]);
        cp16(sbase + G_BHI * 4 + off, &Wh[srcB]);
    }
}

template<int MODE>
__global__ __launch_bounds__(256, 2) void gemmb(const float* __restrict__ bias,
                                                float* __restrict__ C)
{
    extern __shared__ uint32_t smem_g[];
    const uint32_t* Ah = (MODE == 0) ? g_xh  : g_Oh;
    const uint32_t* Wh = (MODE == 0) ? g_wqh : g_woh;

    const int tid  = threadIdx.x;
    const int warp = tid >> 5, lane = tid & 31;
    const int g    = lane >> 2, tg = lane & 3;
    const int wy   = warp >> 2, wx = warp & 3;      // 2 x 4
    const int bm   = blockIdx.y * 128, bn = blockIdx.x * 128;

    float acc[4][4][4];
#pragma unroll
    for (int i = 0; i < 4; i++)
#pragma unroll
        for (int j = 0; j < 4; j++)
#pragma unroll
            for (int r = 0; r < 4; r++) acc[i][j][r] = 0.f;

    const uint32_t sbase = sptr(smem_g);
    const int a_row = wy * 64 + (lane & 15);
    const int a_col = (lane >> 4) * 4;
    const int b_row = wx * 32 + ((lane >> 4) & 1) * 8 + (lane & 7);
    const int b_col = ((lane >> 3) & 1) * 4;

    g_load_stage(sbase,               0, bm, bn, tid, Ah, Wh); CP_COMMIT();
    g_load_stage(sbase + G_STAGE * 4, 1, bm, bn, tid, Ah, Wh); CP_COMMIT();

    int sr = 0, sw = 2;
    for (int kb = 0; kb < 32; kb++) {
        CP_WAIT1();
        __syncthreads();
        if (kb + 2 < 32)
            g_load_stage(sbase + sw * (G_STAGE * 4), kb + 2, bm, bn, tid, Ah, Wh);
        CP_COMMIT();
        const uint32_t st = sbase + sr * (G_STAGE * 4);

#pragma unroll
        for (int ka = 0; ka < 2; ka++) {
            uint32_t kbh[2][4];
#pragma unroll
            for (int nb = 0; nb < 2; nb++) {
                uint32_t off = ((b_row + nb * 16) * GS + ka * 8 + b_col) * 4;
                ldsm4(kbh[nb], st + G_BHI * 4 + off);
            }
#pragma unroll
            for (int ma = 0; ma < 4; ma++) {
                uint32_t off = ((a_row + ma * 16) * GS + ka * 8 + a_col) * 4;
                uint32_t ah[4];
                ldsm4(ah, st + off);
#pragma unroll
                for (int na = 0; na < 4; na++)
                    mma16(acc[ma][na], ah, &kbh[na >> 1][(na & 1) * 2]);
            }
        }
        sr = (sr == 2) ? 0 : sr + 1;
        sw = (sw == 2) ? 0 : sw + 1;
    }

    // ---------- epilogue ----------
#pragma unroll
    for (int ma = 0; ma < 4; ma++) {
        int m0 = bm + wy * 64 + ma * 16 + g;
#pragma unroll
        for (int na = 0; na < 4; na++) {
            int n = bn + wx * 32 + na * 8 + tg * 2;
            float b0v = bias[n], b1v = bias[n + 1];
#pragma unroll
            for (int half = 0; half < 2; half++) {
                int m = m0 + half * 8;
                float vx = acc[ma][na][half * 2 + 0] + b0v;
                float vy = acc[ma][na][half * 2 + 1] + b1v;
                if (MODE == 0) {
                    int bb2 = m >> 11, t = m & (T_ - 1);
                    int sec = n >> 10, rem = n & 1023;
                    int h = rem >> 6, d = rem & 63;
                    int bhh = bb2 * H_ + h;
                    if (sec == 0) {
                        size_t idx = ((size_t)bhh * T_ + t) * 32 + (d >> 1);
                        g_Qh[idx] = pack2(vx * SCALE_LOG2E, vy * SCALE_LOG2E);
                    } else if (sec == 1) {
                        size_t idx = ((size_t)bhh * T_ + t) * 32 + (d >> 1);
                        g_Kh[idx] = pack2(vx, vy);
                    } else {
                        __half hx = __float2half_rn(vx);
                        __half hy = __float2half_rn(vy);
                        size_t ix = (((size_t)bhh * 64 + d) * 1024 + (t >> 1)) * 2 + (t & 1);
                        __half* Vh = reinterpret_cast<__half*>(g_Vh);
                        Vh[ix] = hx; Vh[ix + 2048] = hy;
                    }
                } else {
                    float2 v; v.x = vx; v.y = vy;
                    *(float2*)&C[(size_t)m * N2 + n] = v;
                }
            }
        }
    }
}

// ============ Attention: f16x2 exp2 softmax, 3-stage single-sync ===========
#define ATS 36
#define A_VHI 2304
#define A_STAGE 4608
#define ATTN_SMEM (3 * A_STAGE * 4)

__device__ __forceinline__ void a_load_stage(uint32_t sbase, int bh, int base, int tid)
{
#pragma unroll
    for (int j = 0; j < 2; j++) {
        int i = tid + j * 256;
        int r = i >> 3, c = (i & 7) * 4;
        uint32_t off = (r * ATS + c) * 4;
        size_t srcK = ((size_t)bh * T_ + base + r) * 32 + c;
        size_t srcV = ((size_t)bh * 64 + r) * 1024 + (base >> 1) + c;
        cp16(sbase + off,             &g_Kh[srcK]);
        cp16(sbase + A_VHI * 4 + off, &g_Vh[srcV]);
    }
}

__global__ __launch_bounds__(256, 2) void attnb()
{
    extern __shared__ uint32_t sm[];
    const int tid = threadIdx.x, warp = tid >> 5, lane = tid & 31;
    const int g = lane >> 2, tg = lane & 3;
    const int qb = gridDim.x - 1 - blockIdx.x;      // heavy tiles first
    const int bh = blockIdx.y;
    const int wrow = warp * 16;
    const int qr0  = qb * 128 + wrow;

    const uint32_t sbase = sptr(sm);
    const int f_row = ((lane >> 4) & 1) * 8 + (lane & 7);
    const int f_col = ((lane >> 3) & 1) * 4;

    uint32_t qfh[4][4];
    {
        size_t r0 = ((size_t)bh * T_ + qr0 + g) * 32;
        size_t r8 = r0 + 8 * 32;
#pragma unroll
        for (int ka = 0; ka < 4; ka++) {
            int kp = ka * 8 + tg;
            qfh[ka][0] = g_Qh[r0 + kp];
            qfh[ka][1] = g_Qh[r8 + kp];
            qfh[ka][2] = g_Qh[r0 + kp + 4];
            qfh[ka][3] = g_Qh[r8 + kp + 4];
        }
    }

    float of[8][4];
#pragma unroll
    for (int j = 0; j < 8; j++)
#pragma unroll
        for (int r = 0; r < 4; r++) of[j][r] = 0.f;

    const float NEG_INF = __int_as_float(0xff800000);
    float mrow[2] = {NEG_INF, NEG_INF};
    float lrow[2] = {0.f, 0.f};

    const int ntiles = 2 * qb + 2;
    a_load_stage(sbase,               bh, 0,  tid); CP_COMMIT();
    a_load_stage(sbase + A_STAGE * 4, bh, 64, tid); CP_COMMIT();

    int sr = 0, sw = 2;
    for (int kt = 0; kt < ntiles; kt++) {
        const int base = kt * 64;
        CP_WAIT1();
        __syncthreads();
        if (kt + 2 < ntiles)
            a_load_stage(sbase + sw * (A_STAGE * 4), bh, base + 128, tid);
        CP_COMMIT();
        const uint32_t st = sbase + sr * (A_STAGE * 4);
        sr = (sr == 2) ? 0 : sr + 1;
        sw = (sw == 2) ? 0 : sw + 1;

        if (base > qr0 + 15) continue;

        // ---- S = Q K^T (log2 domain) ----
        float sacc[8][4];
#pragma unroll
        for (int j = 0; j < 8; j++)
#pragma unroll
            for (int r = 0; r < 4; r++) sacc[j][r] = 0.f;

#pragma unroll
        for (int nb = 0; nb < 4; nb++) {
#pragma unroll
            for (int ka = 0; ka < 4; ka++) {
                uint32_t off = ((f_row + nb * 16) * ATS + ka * 8 + f_col) * 4;
                uint32_t kh4[4];
                ldsm4(kh4, st + off);
                mma16(sacc[2 * nb],     qfh[ka], &kh4[0]);
                mma16(sacc[2 * nb + 1], qfh[ka], &kh4[2]);
            }
        }

        // ---- causal mask ----
        if (base + 63 > qr0) {
#pragma unroll
            for (int na = 0; na < 8; na++)
#pragma unroll
                for (int r = 0; r < 4; r++) {
                    int q = qr0 + g + (r >> 1) * 8;
                    int j = base + na * 8 + tg * 2 + (r & 1);
                    if (j > q) sacc[na][r] = NEG_INF;
                }
        }

        // ---- online softmax (base-2): P computed directly in fp16x2 ----
        uint32_t pex[8][2];
#pragma unroll
        for (int h = 0; h < 2; h++) {
            float rm = NEG_INF;
#pragma unroll
            for (int na = 0; na < 8; na++) {
                rm = fmaxf(rm, sacc[na][h * 2 + 0]);
                rm = fmaxf(rm, sacc[na][h * 2 + 1]);
            }
            rm = fmaxf(rm, __shfl_xor_sync(0xffffffffu, rm, 1));
            rm = fmaxf(rm, __shfl_xor_sync(0xffffffffu, rm, 2));
            float mn   = fmaxf(mrow[h], rm);
            float corr = exp2f(mrow[h] - mn);
            mrow[h] = mn;
            float sum = 0.f;
#pragma unroll
            for (int na = 0; na < 8; na++) {
                uint32_t pp = ex2_f16x2(pack2(sacc[na][h * 2 + 0] - mn,
                                              sacc[na][h * 2 + 1] - mn));
                pex[na][h] = pp;
                __half2 hp = *reinterpret_cast<__half2*>(&pp);
                sum += __half2float(hp.x) + __half2float(hp.y);
            }
            sum += __shfl_xor_sync(0xffffffffu, sum, 1);
            sum += __shfl_xor_sync(0xffffffffu, sum, 2);
            lrow[h] = lrow[h] * corr + sum;
#pragma unroll
            for (int na = 0; na < 8; na++) {
                of[na][h * 2 + 0] *= corr;
                of[na][h * 2 + 1] *= corr;
            }
        }

        // ---- O += P V (P fragments already packed) ----
#pragma unroll
        for (int ka = 0; ka < 4; ka++) {
            uint32_t pah[4];
            pah[0] = pex[2 * ka][0];
            pah[1] = pex[2 * ka][1];
            pah[2] = pex[2 * ka + 1][0];
            pah[3] = pex[2 * ka + 1][1];
#pragma unroll
            for (int nb = 0; nb < 4; nb++) {
                uint32_t off = ((f_row + nb * 16) * ATS + ka * 8 + f_col) * 4;
                uint32_t vh4[4];
                ldsm4(vh4, st + A_VHI * 4 + off);
                mma16(of[2 * nb],     pah, &vh4[0]);
                mma16(of[2 * nb + 1], pah, &vh4[2]);
            }
        }
    }

    // ---- finalize ----
    const int bb = bh >> 4, hh = bh & 15;
    float inv0 = 1.f / lrow[0];
    float inv1 = 1.f / lrow[1];
    int q = qb * 128 + wrow + g;
    size_t r0 = (size_t)(bb * T_ + q) * 512 + hh * 32;
    size_t r8 = r0 + 8 * 512;
#pragma unroll
    for (int na = 0; na < 8; na++) {
        int dp = (na * 8 + tg * 2) >> 1;
        g_Oh[r0 + dp] = pack2(of[na][0] * inv0, of[na][1] * inv0);
        g_Oh[r8 + dp] = pack2(of[na][2] * inv1, of[na][3] * inv1);
    }
}

// ---------------- launch ----------------
extern "C" void kernel_launch(void* const* d_in, const int* in_sizes, int n_in,
                              void* d_out, int out_size)
{
    const float* x    = (const float*)d_in[0];
    const float* Wqkv = (const float*)d_in[1];
    const float* bqkv = (const float*)d_in[2];
    const float* Wout = (const float*)d_in[3];
    const float* bout = (const float*)d_in[4];
    float* out = (float*)d_out;

    static bool attr_done = false;
    if (!attr_done) {
        cudaFuncSetAttribute((void*)gemmb<0>, cudaFuncAttributeMaxDynamicSharedMemorySize, GEMM_SMEM);
        cudaFuncSetAttribute((void*)gemmb<1>, cudaFuncAttributeMaxDynamicSharedMemorySize, GEMM_SMEM);
        cudaFuncSetAttribute((void*)attnb,    cudaFuncAttributeMaxDynamicSharedMemorySize, ATTN_SMEM);
        attr_done = true;
    }

    prep_all<<<9216, 256>>>(x, Wqkv, Wout);

    dim3 g1(N1 / 128, M_ / 128);   // (24, 32)
    gemmb<0><<<g1, 256, GEMM_SMEM>>>(bqkv, nullptr);

    dim3 ga(T_ / 128, B_ * H_);    // (16, 32)
    attnb<<<ga, 256, ATTN_SMEM>>>();

    dim3 g2(N2 / 128, M_ / 128);   // (8, 32)
    gemmb<1><<<g2, 256, GEMM_SMEM>>>(bout, out);
}

// round 16
// speedup vs baseline: 1.0591x; 1.0229x over previous
#include <cuda_runtime.h>
#include <cuda_fp16.h>
#include <math.h>
#include <stdint.h>

#define B_  2
#define T_  2048
#define EMB 1024
#define H_  16
#define D_  64
#define M_  (B_ * T_)          // 4096
#define N1  3072
#define N2  1024
#define SCALE_LOG2E 0.1803368801111204f   // 0.125 * log2(e)

// ---------------- scratch (u32 = fp16x2, hi-only) ----------------
__device__ uint32_t g_xh[4096 * 512];        // x  [m][kpair]
__device__ uint32_t g_wqh[3072 * 512];       // Wqkv^T [n][kpair]
__device__ uint32_t g_woh[1024 * 512];       // Wout^T [n][kpair]
__device__ uint32_t g_Qh[2097152];           // [bh][t][32 dpair], pre-scaled
__device__ uint32_t g_Kh[2097152];           // [bh][t][32 dpair]
__device__ uint32_t g_Vh[2097152];           // [bh][64 d][1024 tpair]
__device__ uint32_t g_Oh[2097152];           // [m][512 kpair]

// ---------------- helpers ----------------
__device__ __forceinline__ uint32_t pack2(float x, float y) {   // low=x, high=y
    uint32_t r;
    asm("cvt.rn.f16x2.f32 %0, %1, %2;" : "=r"(r) : "f"(y), "f"(x));
    return r;
}
__device__ __forceinline__ uint32_t ex2_f16x2(uint32_t a) {
    uint32_t r;
    asm("ex2.approx.f16x2 %0, %1;" : "=r"(r) : "r"(a));
    return r;
}
__device__ __forceinline__ void mma16(float* c, const uint32_t* a, const uint32_t* b) {
    asm volatile(
        "mma.sync.aligned.m16n8k16.row.col.f32.f16.f16.f32 "
        "{%0,%1,%2,%3},{%4,%5,%6,%7},{%8,%9},{%0,%1,%2,%3};\n"
        : "+f"(c[0]), "+f"(c[1]), "+f"(c[2]), "+f"(c[3])
        : "r"(a[0]), "r"(a[1]), "r"(a[2]), "r"(a[3]), "r"(b[0]), "r"(b[1]));
}
__device__ __forceinline__ void ldsm4(uint32_t* r, uint32_t saddr) {
    asm volatile("ldmatrix.sync.aligned.m8n8.x4.shared.b16 {%0,%1,%2,%3}, [%4];"
                 : "=r"(r[0]), "=r"(r[1]), "=r"(r[2]), "=r"(r[3]) : "r"(saddr));
}
__device__ __forceinline__ uint32_t sptr(const void* p) {
    return (uint32_t)__cvta_generic_to_shared(p);
}
__device__ __forceinline__ void cp16(uint32_t saddr, const void* g) {
    asm volatile("cp.async.cg.shared.global [%0], [%1], 16;\n" :: "r"(saddr), "l"(g));
}
#define CP_COMMIT() asm volatile("cp.async.commit_group;\n" ::)
#define CP_WAIT1()  asm volatile("cp.async.wait_group 1;\n" ::)

// ---------------- merged prep kernel ----------------
__global__ __launch_bounds__(256) void prep_all(const float* __restrict__ x,
                                                const float* __restrict__ Wqkv,
                                                const float* __restrict__ Wout)
{
    __shared__ uint32_t sh[64][33];
    const int tid = threadIdx.x;
    const int bid = blockIdx.x;

    if (bid < 8192) {
        int i = bid * 256 + tid;
        float2 v = ((const float2*)x)[i];
        g_xh[i] = pack2(v.x, v.y);
        return;
    }
    const float* W;
    uint32_t* Dh;
    int N, n0, kp0;
    if (bid < 8960) {
        int b2 = bid - 8192;
        W = Wqkv; Dh = g_wqh; N = N1;
        n0 = (b2 % 48) * 64;  kp0 = (b2 / 48) * 32;
    } else {
        int b3 = bid - 8960;
        W = Wout; Dh = g_woh; N = N2;
        n0 = (b3 % 16) * 64;  kp0 = (b3 / 16) * 32;
    }
#pragma unroll
    for (int r = 0; r < 8; r++) {
        int kp = r * 4 + (tid >> 6);
        int n  = tid & 63;
        float a = W[(size_t)(2 * (kp0 + kp))     * N + n0 + n];
        float b = W[(size_t)(2 * (kp0 + kp) + 1) * N + n0 + n];
        sh[n][kp] = pack2(a, b);
    }
    __syncthreads();
#pragma unroll
    for (int w = 0; w < 8; w++) {
        int n = w * 8 + (tid >> 5), c = tid & 31;
        Dh[(size_t)(n0 + n) * 512 + kp0 + c] = sh[n][c];
    }
}

// ================= GEMM: 3-stage, load-2-ahead, single sync per k-block ====
#define GS 20
#define G_BHI 2560
#define G_STAGE 5120
#define GEMM_SMEM (3 * G_STAGE * 4)

__device__ __forceinline__ void g_load_stage(uint32_t sbase, int kb, int bm, int bn, int tid,
                                             const uint32_t* __restrict__ Ah,
                                             const uint32_t* __restrict__ Wh)
{
#pragma unroll
    for (int j = 0; j < 2; j++) {
        int idx = tid + j * 256;
        int row = idx >> 2, c = (idx & 3) * 4;
        size_t srcA = (size_t)(bm + row) * 512 + kb * 16 + c;
        size_t srcB = (size_t)(bn + row) * 512 + kb * 16 + c;
        uint32_t off = (row * GS + c) * 4;
        cp16(sbase + off,             &Ah[srcA]);
        cp16(sbase + G_BHI * 4 + off, &Wh[srcB]);
    }
}

template<int MODE>
__global__ __launch_bounds__(256, 2) void gemmb(const float* __restrict__ bias,
                                                float* __restrict__ C)
{
    extern __shared__ uint32_t smem_g[];
    const uint32_t* Ah = (MODE == 0) ? g_xh  : g_Oh;
    const uint32_t* Wh = (MODE == 0) ? g_wqh : g_woh;

    const int tid  = threadIdx.x;
    const int warp = tid >> 5, lane = tid & 31;
    const int g    = lane >> 2, tg = lane & 3;
    const int wy   = warp >> 2, wx = warp & 3;      // 2 x 4
    const int bm   = blockIdx.y * 128, bn = blockIdx.x * 128;

    float acc[4][4][4];
#pragma unroll
    for (int i = 0; i < 4; i++)
#pragma unroll
        for (int j = 0; j < 4; j++)
#pragma unroll
            for (int r = 0; r < 4; r++) acc[i][j][r] = 0.f;

    const uint32_t sbase = sptr(smem_g);
    const int a_row = wy * 64 + (lane & 15);
    const int a_col = (lane >> 4) * 4;
    const int b_row = wx * 32 + ((lane >> 4) & 1) * 8 + (lane & 7);
    const int b_col = ((lane >> 3) & 1) * 4;

    g_load_stage(sbase,               0, bm, bn, tid, Ah, Wh); CP_COMMIT();
    g_load_stage(sbase + G_STAGE * 4, 1, bm, bn, tid, Ah, Wh); CP_COMMIT();

    int sr = 0, sw = 2;
    for (int kb = 0; kb < 32; kb++) {
        CP_WAIT1();
        __syncthreads();
        if (kb + 2 < 32)
            g_load_stage(sbase + sw * (G_STAGE * 4), kb + 2, bm, bn, tid, Ah, Wh);
        CP_COMMIT();
        const uint32_t st = sbase + sr * (G_STAGE * 4);

#pragma unroll
        for (int ka = 0; ka < 2; ka++) {
            uint32_t kbh[2][4];
#pragma unroll
            for (int nb = 0; nb < 2; nb++) {
                uint32_t off = ((b_row + nb * 16) * GS + ka * 8 + b_col) * 4;
                ldsm4(kbh[nb], st + G_BHI * 4 + off);
            }
#pragma unroll
            for (int ma = 0; ma < 4; ma++) {
                uint32_t off = ((a_row + ma * 16) * GS + ka * 8 + a_col) * 4;
                uint32_t ah[4];
                ldsm4(ah, st + off);
#pragma unroll
                for (int na = 0; na < 4; na++)
                    mma16(acc[ma][na], ah, &kbh[na >> 1][(na & 1) * 2]);
            }
        }
        sr = (sr == 2) ? 0 : sr + 1;
        sw = (sw == 2) ? 0 : sw + 1;
    }

    // ---------- epilogue ----------
#pragma unroll
    for (int ma = 0; ma < 4; ma++) {
        int m0 = bm + wy * 64 + ma * 16 + g;
#pragma unroll
        for (int na = 0; na < 4; na++) {
            int n = bn + wx * 32 + na * 8 + tg * 2;
            float b0v = bias[n], b1v = bias[n + 1];
#pragma unroll
            for (int half = 0; half < 2; half++) {
                int m = m0 + half * 8;
                float vx = acc[ma][na][half * 2 + 0] + b0v;
                float vy = acc[ma][na][half * 2 + 1] + b1v;
                if (MODE == 0) {
                    int bb2 = m >> 11, t = m & (T_ - 1);
                    int sec = n >> 10, rem = n & 1023;
                    int h = rem >> 6, d = rem & 63;
                    int bhh = bb2 * H_ + h;
                    if (sec == 0) {
                        size_t idx = ((size_t)bhh * T_ + t) * 32 + (d >> 1);
                        g_Qh[idx] = pack2(vx * SCALE_LOG2E, vy * SCALE_LOG2E);
                    } else if (sec == 1) {
                        size_t idx = ((size_t)bhh * T_ + t) * 32 + (d >> 1);
                        g_Kh[idx] = pack2(vx, vy);
                    } else {
                        __half hx = __float2half_rn(vx);
                        __half hy = __float2half_rn(vy);
                        size_t ix = (((size_t)bhh * 64 + d) * 1024 + (t >> 1)) * 2 + (t & 1);
                        __half* Vh = reinterpret_cast<__half*>(g_Vh);
                        Vh[ix] = hx; Vh[ix + 2048] = hy;
                    }
                } else {
                    float2 v; v.x = vx; v.y = vy;
                    *(float2*)&C[(size_t)m * N2 + n] = v;
                }
            }
        }
    }
}

// ============ Attention: l via P@1 mma, f16x2 exp2, 3-stage single-sync ====
#define ATS 36
#define A_VHI 2304
#define A_STAGE 4608
#define ATTN_SMEM (3 * A_STAGE * 4)

__device__ __forceinline__ void a_load_stage(uint32_t sbase, int bh, int base, int tid)
{
#pragma unroll
    for (int j = 0; j < 2; j++) {
        int i = tid + j * 256;
        int r = i >> 3, c = (i & 7) * 4;
        uint32_t off = (r * ATS + c) * 4;
        size_t srcK = ((size_t)bh * T_ + base + r) * 32 + c;
        size_t srcV = ((size_t)bh * 64 + r) * 1024 + (base >> 1) + c;
        cp16(sbase + off,             &g_Kh[srcK]);
        cp16(sbase + A_VHI * 4 + off, &g_Vh[srcV]);
    }
}

__global__ __launch_bounds__(256, 2) void attnb()
{
    extern __shared__ uint32_t sm[];
    const int tid = threadIdx.x, warp = tid >> 5, lane = tid & 31;
    const int g = lane >> 2, tg = lane & 3;
    const int qb = gridDim.x - 1 - blockIdx.x;      // heavy tiles first
    const int bh = blockIdx.y;
    const int wrow = warp * 16;
    const int qr0  = qb * 128 + wrow;

    const uint32_t sbase = sptr(sm);
    const int f_row = ((lane >> 4) & 1) * 8 + (lane & 7);
    const int f_col = ((lane >> 3) & 1) * 4;

    uint32_t qfh[4][4];
    {
        size_t r0 = ((size_t)bh * T_ + qr0 + g) * 32;
        size_t r8 = r0 + 8 * 32;
#pragma unroll
        for (int ka = 0; ka < 4; ka++) {
            int kp = ka * 8 + tg;
            qfh[ka][0] = g_Qh[r0 + kp];
            qfh[ka][1] = g_Qh[r8 + kp];
            qfh[ka][2] = g_Qh[r0 + kp + 4];
            qfh[ka][3] = g_Qh[r8 + kp + 4];
        }
    }

    float of[8][4];
#pragma unroll
    for (int j = 0; j < 8; j++)
#pragma unroll
        for (int r = 0; r < 4; r++) of[j][r] = 0.f;

    const float NEG_INF = __int_as_float(0xff800000);
    float mrow[2] = {NEG_INF, NEG_INF};
    float lacc[4] = {0.f, 0.f, 0.f, 0.f};   // l via P@ones: [0]=row g, [2]=row g+8
    const uint32_t ONES2[2] = {0x3C003C00u, 0x3C003C00u};

    const int ntiles = 2 * qb + 2;
    a_load_stage(sbase,               bh, 0,  tid); CP_COMMIT();
    a_load_stage(sbase + A_STAGE * 4, bh, 64, tid); CP_COMMIT();

    int sr = 0, sw = 2;
    for (int kt = 0; kt < ntiles; kt++) {
        const int base = kt * 64;
        CP_WAIT1();
        __syncthreads();
        if (kt + 2 < ntiles)
            a_load_stage(sbase + sw * (A_STAGE * 4), bh, base + 128, tid);
        CP_COMMIT();
        const uint32_t st = sbase + sr * (A_STAGE * 4);
        sr = (sr == 2) ? 0 : sr + 1;
        sw = (sw == 2) ? 0 : sw + 1;

        if (base > qr0 + 15) continue;

        // ---- S = Q K^T (log2 domain) ----
        float sacc[8][4];
#pragma unroll
        for (int j = 0; j < 8; j++)
#pragma unroll
            for (int r = 0; r < 4; r++) sacc[j][r] = 0.f;

#pragma unroll
        for (int nb = 0; nb < 4; nb++) {
#pragma unroll
            for (int ka = 0; ka < 4; ka++) {
                uint32_t off = ((f_row + nb * 16) * ATS + ka * 8 + f_col) * 4;
                uint32_t kh4[4];
                ldsm4(kh4, st + off);
                mma16(sacc[2 * nb],     qfh[ka], &kh4[0]);
                mma16(sacc[2 * nb + 1], qfh[ka], &kh4[2]);
            }
        }

        // ---- causal mask ----
        if (base + 63 > qr0) {
#pragma unroll
            for (int na = 0; na < 8; na++)
#pragma unroll
                for (int r = 0; r < 4; r++) {
                    int q = qr0 + g + (r >> 1) * 8;
                    int j = base + na * 8 + tg * 2 + (r & 1);
                    if (j > q) sacc[na][r] = NEG_INF;
                }
        }

        // ---- online softmax (base-2), P in fp16x2 ----
        uint32_t pex[8][2];
#pragma unroll
        for (int h = 0; h < 2; h++) {
            float rm = NEG_INF;
#pragma unroll
            for (int na = 0; na < 8; na++) {
                rm = fmaxf(rm, sacc[na][h * 2 + 0]);
                rm = fmaxf(rm, sacc[na][h * 2 + 1]);
            }
            rm = fmaxf(rm, __shfl_xor_sync(0xffffffffu, rm, 1));
            rm = fmaxf(rm, __shfl_xor_sync(0xffffffffu, rm, 2));
            float mn   = fmaxf(mrow[h], rm);
            float corr = exp2f(mrow[h] - mn);
            mrow[h] = mn;
#pragma unroll
            for (int na = 0; na < 8; na++)
                pex[na][h] = ex2_f16x2(pack2(sacc[na][h * 2 + 0] - mn,
                                             sacc[na][h * 2 + 1] - mn));
            lacc[h * 2 + 0] *= corr;
            lacc[h * 2 + 1] *= corr;
#pragma unroll
            for (int na = 0; na < 8; na++) {
                of[na][h * 2 + 0] *= corr;
                of[na][h * 2 + 1] *= corr;
            }
        }

        // ---- l += P @ ones and O += P V ----
#pragma unroll
        for (int ka = 0; ka < 4; ka++) {
            uint32_t pah[4];
            pah[0] = pex[2 * ka][0];
            pah[1] = pex[2 * ka][1];
            pah[2] = pex[2 * ka + 1][0];
            pah[3] = pex[2 * ka + 1][1];
            mma16(lacc, pah, ONES2);
#pragma unroll
            for (int nb = 0; nb < 4; nb++) {
                uint32_t off = ((f_row + nb * 16) * ATS + ka * 8 + f_col) * 4;
                uint32_t vh4[4];
                ldsm4(vh4, st + A_VHI * 4 + off);
                mma16(of[2 * nb],     pah, &vh4[0]);
                mma16(of[2 * nb + 1], pah, &vh4[2]);
            }
        }
    }

    // ---- finalize (lacc holds full row sums in every lane: no shuffles) ----
    const int bb = bh >> 4, hh = bh & 15;
    float inv0 = 1.f / lacc[0];
    float inv1 = 1.f / lacc[2];
    int q = qb * 128 + wrow + g;
    size_t r0 = (size_t)(bb * T_ + q) * 512 + hh * 32;
    size_t r8 = r0 + 8 * 512;
#pragma unroll
    for (int na = 0; na < 8; na++) {
        int dp = (na * 8 + tg * 2) >> 1;
        g_Oh[r0 + dp] = pack2(of[na][0] * inv0, of[na][1] * inv0);
        g_Oh[r8 + dp] = pack2(of[na][2] * inv1, of[na][3] * inv1);
    }
}

// ---------------- launch ----------------
extern "C" void kernel_launch(void* const* d_in, const int* in_sizes, int n_in,
                              void* d_out, int out_size)
{
    const float* x    = (const float*)d_in[0];
    const float* Wqkv = (const float*)d_in[1];
    const float* bqkv = (const float*)d_in[2];
    const float* Wout = (const float*)d_in[3];
    const float* bout = (const float*)d_in[4];
    float* out = (float*)d_out;

    static bool attr_done = false;
    if (!attr_done) {
        cudaFuncSetAttribute((void*)gemmb<0>, cudaFuncAttributeMaxDynamicSharedMemorySize, GEMM_SMEM);
        cudaFuncSetAttribute((void*)gemmb<1>, cudaFuncAttributeMaxDynamicSharedMemorySize, GEMM_SMEM);
        cudaFuncSetAttribute((void*)attnb,    cudaFuncAttributeMaxDynamicSharedMemorySize, ATTN_SMEM);
        attr_done = true;
    }

    prep_all<<<9216, 256>>>(x, Wqkv, Wout);

    dim3 g1(N1 / 128, M_ / 128);   // (24, 32)
    gemmb<0><<<g1, 256, GEMM_SMEM>>>(bqkv, nullptr);

    dim3 ga(T_ / 128, B_ * H_);    // (16, 32)
    attnb<<<ga, 256, ATTN_SMEM>>>();

    dim3 g2(N2 / 128, M_ / 128);   // (8, 32)
    gemmb<1><<<g2, 256, GEMM_SMEM>>>(bout, out);
}

// round 17
// speedup vs baseline: 1.1662x; 1.1011x over previous
#include <cuda_runtime.h>
#include <cuda_fp16.h>
#include <math.h>
#include <stdint.h>

#define B_  2
#define T_  2048
#define EMB 1024
#define H_  16
#define D_  64
#define M_  (B_ * T_)          // 4096
#define N1  3072
#define N2  1024
#define SCALE_LOG2E 0.1803368801111204f   // 0.125 * log2(e)

// ---------------- scratch (u32 = fp16x2, hi-only) ----------------
__device__ uint32_t g_xh[4096 * 512];        // x  [m][kpair]
__device__ uint32_t g_wqh[3072 * 512];       // Wqkv^T [n][kpair]
__device__ uint32_t g_woh[1024 * 512];       // Wout^T [n][kpair]
__device__ uint32_t g_Qh[2097152];           // [bh][t][32 dpair], pre-scaled
__device__ uint32_t g_Kh[2097152];           // [bh][t][32 dpair]
__device__ uint32_t g_Vh[2097152];           // [bh][64 d][1024 tpair]
__device__ uint32_t g_Oh[2097152];           // [m][512 kpair]

// ---------------- helpers ----------------
__device__ __forceinline__ uint32_t pack2(float x, float y) {   // low=x, high=y
    uint32_t r;
    asm("cvt.rn.f16x2.f32 %0, %1, %2;" : "=r"(r) : "f"(y), "f"(x));
    return r;
}
__device__ __forceinline__ uint32_t ex2_f16x2(uint32_t a) {
    uint32_t r;
    asm("ex2.approx.f16x2 %0, %1;" : "=r"(r) : "r"(a));
    return r;
}
__device__ __forceinline__ void mma16(float* c, const uint32_t* a, const uint32_t* b) {
    asm volatile(
        "mma.sync.aligned.m16n8k16.row.col.f32.f16.f16.f32 "
        "{%0,%1,%2,%3},{%4,%5,%6,%7},{%8,%9},{%0,%1,%2,%3};\n"
        : "+f"(c[0]), "+f"(c[1]), "+f"(c[2]), "+f"(c[3])
        : "r"(a[0]), "r"(a[1]), "r"(a[2]), "r"(a[3]), "r"(b[0]), "r"(b[1]));
}
__device__ __forceinline__ void ldsm4(uint32_t* r, uint32_t saddr) {
    asm volatile("ldmatrix.sync.aligned.m8n8.x4.shared.b16 {%0,%1,%2,%3}, [%4];"
                 : "=r"(r[0]), "=r"(r[1]), "=r"(r[2]), "=r"(r[3]) : "r"(saddr));
}
__device__ __forceinline__ uint32_t sptr(const void* p) {
    return (uint32_t)__cvta_generic_to_shared(p);
}
__device__ __forceinline__ void cp16(uint32_t saddr, const void* g) {
    asm volatile("cp.async.cg.shared.global [%0], [%1], 16;\n" :: "r"(saddr), "l"(g));
}
#define CP_COMMIT() asm volatile("cp.async.commit_group;\n" ::)
#define CP_WAIT1()  asm volatile("cp.async.wait_group 1;\n" ::)

// ---------------- merged prep kernel ----------------
__global__ __launch_bounds__(256) void prep_all(const float* __restrict__ x,
                                                const float* __restrict__ Wqkv,
                                                const float* __restrict__ Wout)
{
    __shared__ uint32_t sh[64][33];
    const int tid = threadIdx.x;
    const int bid = blockIdx.x;

    if (bid < 8192) {
        int i = bid * 256 + tid;
        float2 v = ((const float2*)x)[i];
        g_xh[i] = pack2(v.x, v.y);
        return;
    }
    const float* W;
    uint32_t* Dh;
    int N, n0, kp0;
    if (bid < 8960) {
        int b2 = bid - 8192;
        W = Wqkv; Dh = g_wqh; N = N1;
        n0 = (b2 % 48) * 64;  kp0 = (b2 / 48) * 32;
    } else {
        int b3 = bid - 8960;
        W = Wout; Dh = g_woh; N = N2;
        n0 = (b3 % 16) * 64;  kp0 = (b3 / 16) * 32;
    }
#pragma unroll
    for (int r = 0; r < 8; r++) {
        int kp = r * 4 + (tid >> 6);
        int n  = tid & 63;
        float a = W[(size_t)(2 * (kp0 + kp))     * N + n0 + n];
        float b = W[(size_t)(2 * (kp0 + kp) + 1) * N + n0 + n];
        sh[n][kp] = pack2(a, b);
    }
    __syncthreads();
#pragma unroll
    for (int w = 0; w < 8; w++) {
        int n = w * 8 + (tid >> 5), c = tid & 31;
        Dh[(size_t)(n0 + n) * 512 + kp0 + c] = sh[n][c];
    }
}

// ================= GEMM: 3-stage, load-2-ahead, single sync per k-block ====
#define GS 20
#define G_BHI 2560
#define G_STAGE 5120
#define GEMM_SMEM (3 * G_STAGE * 4)

__device__ __forceinline__ void g_load_stage(uint32_t sbase, int kb, int bm, int bn, int tid,
                                             const uint32_t* __restrict__ Ah,
                                             const uint32_t* __restrict__ Wh)
{
#pragma unroll
    for (int j = 0; j < 2; j++) {
        int idx = tid + j * 256;
        int row = idx >> 2, c = (idx & 3) * 4;
        size_t srcA = (size_t)(bm + row) * 512 + kb * 16 + c;
        size_t srcB = (size_t)(bn + row) * 512 + kb * 16 + c;
        uint32_t off = (row * GS + c) * 4;
        cp16(sbase + off,             &Ah[srcA]);
        cp16(sbase + G_BHI * 4 + off, &Wh[srcB]);
    }
}

template<int MODE>
__global__ __launch_bounds__(256, 2) void gemmb(const float* __restrict__ bias,
                                                float* __restrict__ C)
{
    extern __shared__ uint32_t smem_g[];
    const uint32_t* Ah = (MODE == 0) ? g_xh  : g_Oh;
    const uint32_t* Wh = (MODE == 0) ? g_wqh : g_woh;

    const int tid  = threadIdx.x;
    const int warp = tid >> 5, lane = tid & 31;
    const int g    = lane >> 2, tg = lane & 3;
    const int wy   = warp >> 2, wx = warp & 3;      // 2 x 4
    const int bm   = blockIdx.y * 128, bn = blockIdx.x * 128;

    float acc[4][4][4];
#pragma unroll
    for (int i = 0; i < 4; i++)
#pragma unroll
        for (int j = 0; j < 4; j++)
#pragma unroll
            for (int r = 0; r < 4; r++) acc[i][j][r] = 0.f;

    const uint32_t sbase = sptr(smem_g);
    const int a_row = wy * 64 + (lane & 15);
    const int a_col = (lane >> 4) * 4;
    const int b_row = wx * 32 + ((lane >> 4) & 1) * 8 + (lane & 7);
    const int b_col = ((lane >> 3) & 1) * 4;

    g_load_stage(sbase,               0, bm, bn, tid, Ah, Wh); CP_COMMIT();
    g_load_stage(sbase + G_STAGE * 4, 1, bm, bn, tid, Ah, Wh); CP_COMMIT();

    int sr = 0, sw = 2;
    for (int kb = 0; kb < 32; kb++) {
        CP_WAIT1();
        __syncthreads();
        if (kb + 2 < 32)
            g_load_stage(sbase + sw * (G_STAGE * 4), kb + 2, bm, bn, tid, Ah, Wh);
        CP_COMMIT();
        const uint32_t st = sbase + sr * (G_STAGE * 4);

#pragma unroll
        for (int ka = 0; ka < 2; ka++) {
            uint32_t kbh[2][4];
#pragma unroll
            for (int nb = 0; nb < 2; nb++) {
                uint32_t off = ((b_row + nb * 16) * GS + ka * 8 + b_col) * 4;
                ldsm4(kbh[nb], st + G_BHI * 4 + off);
            }
#pragma unroll
            for (int ma = 0; ma < 4; ma++) {
                uint32_t off = ((a_row + ma * 16) * GS + ka * 8 + a_col) * 4;
                uint32_t ah[4];
                ldsm4(ah, st + off);
#pragma unroll
                for (int na = 0; na < 4; na++)
                    mma16(acc[ma][na], ah, &kbh[na >> 1][(na & 1) * 2]);
            }
        }
        sr = (sr == 2) ? 0 : sr + 1;
        sw = (sw == 2) ? 0 : sw + 1;
    }

    // ---------- epilogue ----------
#pragma unroll
    for (int ma = 0; ma < 4; ma++) {
        int m0 = bm + wy * 64 + ma * 16 + g;
#pragma unroll
        for (int na = 0; na < 4; na++) {
            int n = bn + wx * 32 + na * 8 + tg * 2;
            float b0v = bias[n], b1v = bias[n + 1];
#pragma unroll
            for (int half = 0; half < 2; half++) {
                int m = m0 + half * 8;
                float vx = acc[ma][na][half * 2 + 0] + b0v;
                float vy = acc[ma][na][half * 2 + 1] + b1v;
                if (MODE == 0) {
                    int bb2 = m >> 11, t = m & (T_ - 1);
                    int sec = n >> 10, rem = n & 1023;
                    int h = rem >> 6, d = rem & 63;
                    int bhh = bb2 * H_ + h;
                    if (sec == 0) {
                        size_t idx = ((size_t)bhh * T_ + t) * 32 + (d >> 1);
                        g_Qh[idx] = pack2(vx * SCALE_LOG2E, vy * SCALE_LOG2E);
                    } else if (sec == 1) {
                        size_t idx = ((size_t)bhh * T_ + t) * 32 + (d >> 1);
                        g_Kh[idx] = pack2(vx, vy);
                    } else {
                        __half hx = __float2half_rn(vx);
                        __half hy = __float2half_rn(vy);
                        size_t ix = (((size_t)bhh * 64 + d) * 1024 + (t >> 1)) * 2 + (t & 1);
                        __half* Vh = reinterpret_cast<__half*>(g_Vh);
                        Vh[ix] = hx; Vh[ix + 2048] = hy;
                    }
                } else {
                    float2 v; v.x = vx; v.y = vy;
                    *(float2*)&C[(size_t)m * N2 + n] = v;
                }
            }
        }
    }
}

// ============ Attention: LPT grid, diag-skip, l via P@1, f16x2 exp2 ========
#define ATS 36
#define A_VHI 2304
#define A_STAGE 4608
#define ATTN_SMEM (3 * A_STAGE * 4)

__device__ __forceinline__ void a_load_stage(uint32_t sbase, int bh, int base, int tid)
{
#pragma unroll
    for (int j = 0; j < 2; j++) {
        int i = tid + j * 256;
        int r = i >> 3, c = (i & 7) * 4;
        uint32_t off = (r * ATS + c) * 4;
        size_t srcK = ((size_t)bh * T_ + base + r) * 32 + c;
        size_t srcV = ((size_t)bh * 64 + r) * 1024 + (base >> 1) + c;
        cp16(sbase + off,             &g_Kh[srcK]);
        cp16(sbase + A_VHI * 4 + off, &g_Vh[srcV]);
    }
}

__global__ __launch_bounds__(256, 2) void attnb()
{
    extern __shared__ uint32_t sm[];
    const int tid = threadIdx.x, warp = tid >> 5, lane = tid & 31;
    const int g = lane >> 2, tg = lane & 3;
    const int bh = blockIdx.x;                      // LPT: heavy qb across all heads first
    const int qb = gridDim.y - 1 - blockIdx.y;
    const int wrow = warp * 16;
    const int qr0  = qb * 128 + wrow;

    const uint32_t sbase = sptr(sm);
    const int f_row = ((lane >> 4) & 1) * 8 + (lane & 7);
    const int f_col = ((lane >> 3) & 1) * 4;

    uint32_t qfh[4][4];
    {
        size_t r0 = ((size_t)bh * T_ + qr0 + g) * 32;
        size_t r8 = r0 + 8 * 32;
#pragma unroll
        for (int ka = 0; ka < 4; ka++) {
            int kp = ka * 8 + tg;
            qfh[ka][0] = g_Qh[r0 + kp];
            qfh[ka][1] = g_Qh[r8 + kp];
            qfh[ka][2] = g_Qh[r0 + kp + 4];
            qfh[ka][3] = g_Qh[r8 + kp + 4];
        }
    }

    float of[8][4];
#pragma unroll
    for (int j = 0; j < 8; j++)
#pragma unroll
        for (int r = 0; r < 4; r++) of[j][r] = 0.f;

    const float NEG_INF = __int_as_float(0xff800000);
    float mrow[2] = {NEG_INF, NEG_INF};
    float lacc[4] = {0.f, 0.f, 0.f, 0.f};
    const uint32_t ONES2[2] = {0x3C003C00u, 0x3C003C00u};

    const int ntiles = 2 * qb + 2;
    a_load_stage(sbase,               bh, 0,  tid); CP_COMMIT();
    a_load_stage(sbase + A_STAGE * 4, bh, 64, tid); CP_COMMIT();

    int sr = 0, sw = 2;
    for (int kt = 0; kt < ntiles; kt++) {
        const int base = kt * 64;
        CP_WAIT1();
        __syncthreads();
        if (kt + 2 < ntiles)
            a_load_stage(sbase + sw * (A_STAGE * 4), bh, base + 128, tid);
        CP_COMMIT();
        const uint32_t st = sbase + sr * (A_STAGE * 4);
        sr = (sr == 2) ? 0 : sr + 1;
        sw = (sw == 2) ? 0 : sw + 1;

        if (base > qr0 + 15) continue;
        const int klim = qr0 + 15 - base;   // last unmasked key offset in tile

        // ---- S = Q K^T (skip fully-masked key blocks) ----
        float sacc[8][4];
#pragma unroll
        for (int j = 0; j < 8; j++)
#pragma unroll
            for (int r = 0; r < 4; r++) sacc[j][r] = 0.f;

#pragma unroll
        for (int nb = 0; nb < 4; nb++) {
            if (nb * 16 > klim) break;      // warp-uniform
#pragma unroll
            for (int ka = 0; ka < 4; ka++) {
                uint32_t off = ((f_row + nb * 16) * ATS + ka * 8 + f_col) * 4;
                uint32_t kh4[4];
                ldsm4(kh4, st + off);
                mma16(sacc[2 * nb],     qfh[ka], &kh4[0]);
                mma16(sacc[2 * nb + 1], qfh[ka], &kh4[2]);
            }
        }

        // ---- causal mask (covers skipped atoms too: sacc==0 -> NEG_INF) ----
        if (base + 63 > qr0) {
#pragma unroll
            for (int na = 0; na < 8; na++)
#pragma unroll
                for (int r = 0; r < 4; r++) {
                    int q = qr0 + g + (r >> 1) * 8;
                    int j = base + na * 8 + tg * 2 + (r & 1);
                    if (j > q) sacc[na][r] = NEG_INF;
                }
        }

        // ---- online softmax (base-2), P in fp16x2 ----
        uint32_t pex[8][2];
#pragma unroll
        for (int h = 0; h < 2; h++) {
            float rm = NEG_INF;
#pragma unroll
            for (int na = 0; na < 8; na++) {
                rm = fmaxf(rm, sacc[na][h * 2 + 0]);
                rm = fmaxf(rm, sacc[na][h * 2 + 1]);
            }
            rm = fmaxf(rm, __shfl_xor_sync(0xffffffffu, rm, 1));
            rm = fmaxf(rm, __shfl_xor_sync(0xffffffffu, rm, 2));
            float mn   = fmaxf(mrow[h], rm);
            float corr = exp2f(mrow[h] - mn);
            mrow[h] = mn;
#pragma unroll
            for (int na = 0; na < 8; na++)
                pex[na][h] = ex2_f16x2(pack2(sacc[na][h * 2 + 0] - mn,
                                             sacc[na][h * 2 + 1] - mn));
            lacc[h * 2 + 0] *= corr;
            lacc[h * 2 + 1] *= corr;
#pragma unroll
            for (int na = 0; na < 8; na++) {
                of[na][h * 2 + 0] *= corr;
                of[na][h * 2 + 1] *= corr;
            }
        }

        // ---- l += P @ ones and O += P V (skip fully-masked key chunks) ----
#pragma unroll
        for (int ka = 0; ka < 4; ka++) {
            if (ka * 16 > klim) break;      // warp-uniform; pex there is 0
            uint32_t pah[4];
            pah[0] = pex[2 * ka][0];
            pah[1] = pex[2 * ka][1];
            pah[2] = pex[2 * ka + 1][0];
            pah[3] = pex[2 * ka + 1][1];
            mma16(lacc, pah, ONES2);
#pragma unroll
            for (int nb = 0; nb < 4; nb++) {
                uint32_t off = ((f_row + nb * 16) * ATS + ka * 8 + f_col) * 4;
                uint32_t vh4[4];
                ldsm4(vh4, st + A_VHI * 4 + off);
                mma16(of[2 * nb],     pah, &vh4[0]);
                mma16(of[2 * nb + 1], pah, &vh4[2]);
            }
        }
    }

    // ---- finalize ----
    const int bb = bh >> 4, hh = bh & 15;
    float inv0 = 1.f / lacc[0];
    float inv1 = 1.f / lacc[2];
    int q = qb * 128 + wrow + g;
    size_t r0 = (size_t)(bb * T_ + q) * 512 + hh * 32;
    size_t r8 = r0 + 8 * 512;
#pragma unroll
    for (int na = 0; na < 8; na++) {
        int dp = (na * 8 + tg * 2) >> 1;
        g_Oh[r0 + dp] = pack2(of[na][0] * inv0, of[na][1] * inv0);
        g_Oh[r8 + dp] = pack2(of[na][2] * inv1, of[na][3] * inv1);
    }
}

// ---------------- launch ----------------
extern "C" void kernel_launch(void* const* d_in, const int* in_sizes, int n_in,
                              void* d_out, int out_size)
{
    const float* x    = (const float*)d_in[0];
    const float* Wqkv = (const float*)d_in[1];
    const float* bqkv = (const float*)d_in[2];
    const float* Wout = (const float*)d_in[3];
    const float* bout = (const float*)d_in[4];
    float* out = (float*)d_out;

    static bool attr_done = false;
    if (!attr_done) {
        cudaFuncSetAttribute((void*)gemmb<0>, cudaFuncAttributeMaxDynamicSharedMemorySize, GEMM_SMEM);
        cudaFuncSetAttribute((void*)gemmb<1>, cudaFuncAttributeMaxDynamicSharedMemorySize, GEMM_SMEM);
        cudaFuncSetAttribute((void*)attnb,    cudaFuncAttributeMaxDynamicSharedMemorySize, ATTN_SMEM);
        attr_done = true;
    }

    prep_all<<<9216, 256>>>(x, Wqkv, Wout);

    dim3 g1(N1 / 128, M_ / 128);   // (24, 32)
    gemmb<0><<<g1, 256, GEMM_SMEM>>>(bqkv, nullptr);

    dim3 ga(B_ * H_, T_ / 128);    // (32, 16) — LPT order over qb bands
    attnb<<<ga, 256, ATTN_SMEM>>>();

    dim3 g2(N2 / 128, M_ / 128);   // (8, 32)
    gemmb<1><<<g2, 256, GEMM_SMEM>>>(bout, out);
}